// round 3
// baseline (speedup 1.0000x reference)
#include <cuda_runtime.h>
#include <stdint.h>
#include <math.h>

#define T_TOK 1024
#define H_DIM 2048
#define F_DIM 4096
#define E_EXP 8
#define ROWS_CAP 3072
#define MTILES (ROWS_CAP / 128)   // 24

// ---------------- scratch (device globals; allocation-free) ----------------
__device__ int   g_cnt[E_EXP];
__device__ int   g_fill[E_EXP];
__device__ int   g_off[E_EXP + 1];
__device__ int   g_tile_e[MTILES];
__device__ int   g_rows[ROWS_CAP];          // row -> token
__device__ float g_rw[ROWS_CAP];            // row -> gate weight
__device__ int   g_pos[T_TOK * 2];          // (token,slot) -> row
__device__ int   g_te[T_TOK * 2];           // (token,slot) -> expert
__device__ float g_tw[T_TOK * 2];           // (token,slot) -> weight
__device__ float g_A[(size_t)ROWS_CAP * F_DIM];   // 50 MB
__device__ float g_Y[(size_t)ROWS_CAP * H_DIM];   // 25 MB

__device__ __forceinline__ uint32_t f2tf(float f) {
    uint32_t u;
    asm("cvt.rna.tf32.f32 %0, %1;" : "=r"(u) : "f"(f));
    return u;
}
__device__ __forceinline__ float silu_f(float v) { return v / (1.0f + expf(-v)); }

__device__ __forceinline__ void mma_tf32(float& c0, float& c1, float& c2, float& c3,
                                         uint32_t a0, uint32_t a1, uint32_t a2, uint32_t a3,
                                         uint32_t b0, uint32_t b1) {
    asm volatile(
        "mma.sync.aligned.m16n8k8.row.col.f32.tf32.tf32.f32 "
        "{%0,%1,%2,%3}, {%4,%5,%6,%7}, {%8,%9}, {%0,%1,%2,%3};\n"
        : "+f"(c0), "+f"(c1), "+f"(c2), "+f"(c3)
        : "r"(a0), "r"(a1), "r"(a2), "r"(a3), "r"(b0), "r"(b1));
}

// --------------------------- routing pipeline ------------------------------
__global__ void init_kernel() {
    if (threadIdx.x < E_EXP) g_cnt[threadIdx.x] = 0;
}

// one warp per token: logits -> top2 -> weights, counts
__global__ void gate_kernel(const float* __restrict__ x, const float* __restrict__ wg) {
    int t = blockIdx.x * (blockDim.x >> 5) + (threadIdx.x >> 5);
    int lane = threadIdx.x & 31;
    if (t >= T_TOK) return;

    const float* xr = x + (size_t)t * H_DIM;
    float acc[E_EXP];
#pragma unroll
    for (int e = 0; e < E_EXP; e++) acc[e] = 0.0f;
    for (int h = lane; h < H_DIM; h += 32) {
        float xv = xr[h];
        const float* wrow = wg + (size_t)h * E_EXP;
#pragma unroll
        for (int e = 0; e < E_EXP; e++) acc[e] += xv * wrow[e];
    }
#pragma unroll
    for (int e = 0; e < E_EXP; e++) {
#pragma unroll
        for (int o = 16; o > 0; o >>= 1) acc[e] += __shfl_xor_sync(0xffffffffu, acc[e], o);
    }
    if (lane == 0) {
        int i0 = 0; float v0 = acc[0];
#pragma unroll
        for (int e = 1; e < E_EXP; e++) if (acc[e] > v0) { v0 = acc[e]; i0 = e; }
        int i1 = -1; float v1 = -INFINITY;
#pragma unroll
        for (int e = 0; e < E_EXP; e++) if (e != i0 && acc[e] > v1) { v1 = acc[e]; i1 = e; }
        float w0 = 1.0f / (1.0f + expf(v1 - v0));
        g_te[2 * t] = i0;     g_tw[2 * t] = w0;
        g_te[2 * t + 1] = i1; g_tw[2 * t + 1] = 1.0f - w0;
        atomicAdd(&g_cnt[i0], 1);
        atomicAdd(&g_cnt[i1], 1);
    }
}

// single block: 128-aligned segment offsets, tile->expert map, init rows
__global__ void route_kernel() {
    __shared__ int soff[E_EXP + 1];
    if (threadIdx.x == 0) {
        int o = 0;
#pragma unroll
        for (int e = 0; e < E_EXP; e++) {
            soff[e] = o;
            o += (g_cnt[e] + 127) & ~127;
        }
        soff[E_EXP] = o;
#pragma unroll
        for (int e = 0; e <= E_EXP; e++) g_off[e] = soff[e];
#pragma unroll
        for (int e = 0; e < E_EXP; e++) g_fill[e] = 0;
    }
    __syncthreads();
    if (threadIdx.x < MTILES) {
        int i = threadIdx.x;
        int e = -1;
#pragma unroll
        for (int ee = 0; ee < E_EXP; ee++)
            if (i * 128 >= soff[ee] && i * 128 < soff[ee + 1]) e = ee;
        g_tile_e[i] = e;
    }
    for (int r = threadIdx.x; r < ROWS_CAP; r += blockDim.x) {
        g_rows[r] = 0;
        g_rw[r] = 0.0f;
    }
}

__global__ void scatter_kernel() {
    int t = blockIdx.x * blockDim.x + threadIdx.x;
    if (t >= T_TOK) return;
#pragma unroll
    for (int s = 0; s < 2; s++) {
        int e = g_te[2 * t + s];
        int r = g_off[e] + atomicAdd(&g_fill[e], 1);
        g_rows[r] = t;
        g_rw[r] = g_tw[2 * t + s];
        g_pos[2 * t + s] = r;
    }
}

// ---------------------------------------------------------------------------
// tf32 GEMM on permuted rows. 128x128x32 tile, 256 threads (4Mx2N warps),
// double-buffered smem + register prefetch (1 __syncthreads per K-tile).
//
// mode 0: C = x[rows] @ w1[e];  g_A[r, n] = silu(C)
// mode 1: C = x[rows] @ w3[e];  g_A[r, n] *= C * g_rw[r]
// mode 2: C = g_A @ w2[e];      g_Y[r, n] = C
// ---------------------------------------------------------------------------
#define AS_WORDS 4608   // 128 * 36
#define BS_WORDS 4224   // 32 * 132
#define SMEM_BYTES ((2 * AS_WORDS + 2 * BS_WORDS) * 4)

__global__ __launch_bounds__(256) void gemm_kernel(const float* __restrict__ X,
                                                   const float* __restrict__ W,
                                                   int K, int lda, int ldb, int mode) {
    extern __shared__ uint32_t smem[];
    uint32_t* As0 = smem;                       // [2][128][36]
    uint32_t* Bs0 = smem + 2 * AS_WORDS;        // [2][32][132]

    const int my = blockIdx.y;
    const int e = g_tile_e[my];
    if (e < 0) return;

    const int tid = threadIdx.x;
    const int warp = tid >> 5;
    const int lane = tid & 31;
    const int wm = warp & 3;
    const int wn = warp >> 2;
    const int g = lane >> 2;
    const int tg = lane & 3;

    const int bm = my * 128;
    const int bn = blockIdx.x * 128;

    const float* Bbase = W + (size_t)e * (size_t)K * (size_t)ldb;

    // per-thread staging sources (fixed rows, advance along K)
    const float* aptr[4];
    const float* bptr[4];
#pragma unroll
    for (int i = 0; i < 4; i++) {
        int slot = tid + i * 256;
        int r = slot >> 3;
        int c4 = (slot & 7) << 2;
        if (mode <= 1)
            aptr[i] = X + (size_t)g_rows[bm + r] * lda + c4;
        else
            aptr[i] = g_A + (size_t)(bm + r) * lda + c4;
    }
#pragma unroll
    for (int i = 0; i < 4; i++) {
        int slot = tid + i * 256;
        int r = slot >> 5;
        int c4 = (slot & 31) << 2;
        bptr[i] = Bbase + (size_t)r * ldb + bn + c4;
    }

    float c[2][8][4];
#pragma unroll
    for (int mi = 0; mi < 2; mi++)
#pragma unroll
        for (int ni = 0; ni < 8; ni++)
#pragma unroll
            for (int q = 0; q < 4; q++) c[mi][ni][q] = 0.0f;

    // preload first K-tile into registers
    float4 ra[4], rb[4];
#pragma unroll
    for (int i = 0; i < 4; i++) {
        ra[i] = *reinterpret_cast<const float4*>(aptr[i]);
        rb[i] = *reinterpret_cast<const float4*>(bptr[i]);
        aptr[i] += 32;
        bptr[i] += (size_t)32 * ldb;
    }

    int buf = 0;
    for (int k0 = 0; k0 < K; k0 += 32) {
        // store staged registers -> smem[buf]
        uint32_t* Asb = As0 + buf * AS_WORDS;
        uint32_t* Bsb = Bs0 + buf * BS_WORDS;
#pragma unroll
        for (int i = 0; i < 4; i++) {
            int slot = tid + i * 256;
            int r = slot >> 3;
            int c4 = (slot & 7) << 2;
            uint4 u = make_uint4(f2tf(ra[i].x), f2tf(ra[i].y), f2tf(ra[i].z), f2tf(ra[i].w));
            *reinterpret_cast<uint4*>(Asb + r * 36 + c4) = u;
        }
#pragma unroll
        for (int i = 0; i < 4; i++) {
            int slot = tid + i * 256;
            int r = slot >> 5;
            int c4 = (slot & 31) << 2;
            uint4 u = make_uint4(f2tf(rb[i].x), f2tf(rb[i].y), f2tf(rb[i].z), f2tf(rb[i].w));
            *reinterpret_cast<uint4*>(Bsb + r * 132 + c4) = u;
        }
        __syncthreads();

        // prefetch next K-tile while computing this one
        if (k0 + 32 < K) {
#pragma unroll
            for (int i = 0; i < 4; i++) {
                ra[i] = *reinterpret_cast<const float4*>(aptr[i]);
                rb[i] = *reinterpret_cast<const float4*>(bptr[i]);
                aptr[i] += 32;
                bptr[i] += (size_t)32 * ldb;
            }
        }

#pragma unroll
        for (int ks = 0; ks < 4; ks++) {
            const int kk = ks * 8;
            uint32_t a[2][4];
            uint32_t b[8][2];
#pragma unroll
            for (int mi = 0; mi < 2; mi++) {
                int r0 = wm * 32 + mi * 16;
                a[mi][0] = Asb[(r0 + g) * 36 + kk + tg];
                a[mi][1] = Asb[(r0 + 8 + g) * 36 + kk + tg];
                a[mi][2] = Asb[(r0 + g) * 36 + kk + tg + 4];
                a[mi][3] = Asb[(r0 + 8 + g) * 36 + kk + tg + 4];
            }
#pragma unroll
            for (int ni = 0; ni < 8; ni++) {
                int col = wn * 64 + ni * 8 + g;
                b[ni][0] = Bsb[(kk + tg) * 132 + col];
                b[ni][1] = Bsb[(kk + tg + 4) * 132 + col];
            }
#pragma unroll
            for (int mi = 0; mi < 2; mi++)
#pragma unroll
                for (int ni = 0; ni < 8; ni++)
                    mma_tf32(c[mi][ni][0], c[mi][ni][1], c[mi][ni][2], c[mi][ni][3],
                             a[mi][0], a[mi][1], a[mi][2], a[mi][3],
                             b[ni][0], b[ni][1]);
        }
        buf ^= 1;
        __syncthreads();
    }

    // epilogue; c0->(r0,cl), c1->(r0,cl+1), c2->(r0+8,cl), c3->(r0+8,cl+1)
    const int r_base = bm + wm * 32;
    const int c_base = bn + wn * 64;

    if (mode == 0) {
#pragma unroll
        for (int mi = 0; mi < 2; mi++) {
            int r0 = r_base + mi * 16 + g;
            size_t o0 = (size_t)r0 * F_DIM;
            size_t o1 = (size_t)(r0 + 8) * F_DIM;
#pragma unroll
            for (int ni = 0; ni < 8; ni++) {
                int cl = c_base + ni * 8 + 2 * tg;
                float2 v0 = make_float2(silu_f(c[mi][ni][0]), silu_f(c[mi][ni][1]));
                float2 v1 = make_float2(silu_f(c[mi][ni][2]), silu_f(c[mi][ni][3]));
                *reinterpret_cast<float2*>(g_A + o0 + cl) = v0;
                *reinterpret_cast<float2*>(g_A + o1 + cl) = v1;
            }
        }
    } else if (mode == 1) {
#pragma unroll
        for (int mi = 0; mi < 2; mi++) {
            int r0 = r_base + mi * 16 + g;
            float wa = g_rw[r0];
            float wb = g_rw[r0 + 8];
            size_t o0 = (size_t)r0 * F_DIM;
            size_t o1 = (size_t)(r0 + 8) * F_DIM;
#pragma unroll
            for (int ni = 0; ni < 8; ni++) {
                int cl = c_base + ni * 8 + 2 * tg;
                float2 p0 = *reinterpret_cast<const float2*>(g_A + o0 + cl);
                float2 p1 = *reinterpret_cast<const float2*>(g_A + o1 + cl);
                p0.x *= c[mi][ni][0] * wa;
                p0.y *= c[mi][ni][1] * wa;
                p1.x *= c[mi][ni][2] * wb;
                p1.y *= c[mi][ni][3] * wb;
                *reinterpret_cast<float2*>(g_A + o0 + cl) = p0;
                *reinterpret_cast<float2*>(g_A + o1 + cl) = p1;
            }
        }
    } else {
#pragma unroll
        for (int mi = 0; mi < 2; mi++) {
            int r0 = r_base + mi * 16 + g;
            size_t o0 = (size_t)r0 * H_DIM;
            size_t o1 = (size_t)(r0 + 8) * H_DIM;
#pragma unroll
            for (int ni = 0; ni < 8; ni++) {
                int cl = c_base + ni * 8 + 2 * tg;
                float2 v0 = make_float2(c[mi][ni][0], c[mi][ni][1]);
                float2 v1 = make_float2(c[mi][ni][2], c[mi][ni][3]);
                *reinterpret_cast<float2*>(g_Y + o0 + cl) = v0;
                *reinterpret_cast<float2*>(g_Y + o1 + cl) = v1;
            }
        }
    }
}

// out[t] = Y[pos(t,0)] + Y[pos(t,1)]  (weights already folded into g_A)
__global__ void combine_kernel(float* __restrict__ out) {
    int i = blockIdx.x * blockDim.x + threadIdx.x;  // one float4 per thread
    int t = i / (H_DIM / 4);
    int h = (i % (H_DIM / 4)) * 4;
    int r0 = g_pos[2 * t];
    int r1 = g_pos[2 * t + 1];
    float4 a = *reinterpret_cast<const float4*>(g_Y + (size_t)r0 * H_DIM + h);
    float4 b = *reinterpret_cast<const float4*>(g_Y + (size_t)r1 * H_DIM + h);
    float4 r = make_float4(a.x + b.x, a.y + b.y, a.z + b.z, a.w + b.w);
    *reinterpret_cast<float4*>(out + (size_t)t * H_DIM + h) = r;
}

extern "C" void kernel_launch(void* const* d_in, const int* in_sizes, int n_in,
                              void* d_out, int out_size) {
    const float* x  = (const float*)d_in[0];  // (1,1,T,H)
    const float* wg = (const float*)d_in[1];  // (H,E)
    const float* w1 = (const float*)d_in[2];  // (E,H,F)
    const float* w3 = (const float*)d_in[3];  // (E,H,F)
    const float* w2 = (const float*)d_in[4];  // (E,F,H)
    float* out = (float*)d_out;

    cudaFuncSetAttribute(gemm_kernel, cudaFuncAttributeMaxDynamicSharedMemorySize, SMEM_BYTES);

    init_kernel<<<1, 32>>>();
    gate_kernel<<<T_TOK / 8, 256>>>(x, wg);
    route_kernel<<<1, 256>>>();
    scatter_kernel<<<T_TOK / 256, 256>>>();

    dim3 g1(F_DIM / 128, MTILES);
    gemm_kernel<<<g1, 256, SMEM_BYTES>>>(x, w1, H_DIM, H_DIM, F_DIM, 0);
    gemm_kernel<<<g1, 256, SMEM_BYTES>>>(x, w3, H_DIM, H_DIM, F_DIM, 1);

    dim3 g2(H_DIM / 128, MTILES);
    gemm_kernel<<<g2, 256, SMEM_BYTES>>>(nullptr, w2, F_DIM, F_DIM, H_DIM, 2);

    combine_kernel<<<(T_TOK * H_DIM / 4) / 256, 256>>>(out);
}

// round 5
// speedup vs baseline: 1.3377x; 1.3377x over previous
#include <cuda_runtime.h>
#include <stdint.h>
#include <math.h>

#define T_TOK 1024
#define H_DIM 2048
#define F_DIM 4096
#define E_EXP 8
#define ROWS_CAP 3072
#define MTILES (ROWS_CAP / 128)   // 24
#define STAGES 3

#define AS_W 4608   // 128 * 36 words
#define BS_W 4352   // 32 * 136 words
#define STG_W (AS_W + BS_W)
#define SMEM_BYTES (STAGES * STG_W * 4)

// ---------------- scratch ----------------
__device__ __align__(256) float g_X[(size_t)ROWS_CAP * H_DIM];
__device__ __align__(256) float g_A[(size_t)ROWS_CAP * F_DIM];
__device__ __align__(256) float g_Y[(size_t)ROWS_CAP * H_DIM];
__device__ int   g_cnt[E_EXP];
__device__ int   g_fill[E_EXP];
__device__ int   g_off[E_EXP + 1];
__device__ int   g_tile_e[MTILES];
__device__ int   g_rows[ROWS_CAP];
__device__ float g_rw[ROWS_CAP];
__device__ int   g_pos[T_TOK * 2];
__device__ int   g_te[T_TOK * 2];
__device__ float g_tw[T_TOK * 2];

__device__ __forceinline__ uint32_t f2tf(float f) {
    uint32_t u;
    asm("cvt.rna.tf32.f32 %0, %1;" : "=r"(u) : "f"(f));
    return u;
}
__device__ __forceinline__ float silu_f(float v) { return v / (1.0f + expf(-v)); }

__device__ __forceinline__ uint32_t smem_u32(const void* p) {
    uint32_t a;
    asm("{ .reg .u64 t; cvta.to.shared.u64 t, %1; cvt.u32.u64 %0, t; }" : "=r"(a) : "l"(p));
    return a;
}
__device__ __forceinline__ void cp16(uint32_t dst, const float* src) {
    asm volatile("cp.async.cg.shared.global [%0], [%1], 16;" :: "r"(dst), "l"(src));
}
#define CP_COMMIT() asm volatile("cp.async.commit_group;" ::: "memory")
#define CP_WAIT1()  asm volatile("cp.async.wait_group 1;" ::: "memory")

__device__ __forceinline__ void mma_tf32(float& c0, float& c1, float& c2, float& c3,
                                         uint32_t a0, uint32_t a1, uint32_t a2, uint32_t a3,
                                         uint32_t b0, uint32_t b1) {
    asm volatile(
        "mma.sync.aligned.m16n8k8.row.col.f32.tf32.tf32.f32 "
        "{%0,%1,%2,%3}, {%4,%5,%6,%7}, {%8,%9}, {%0,%1,%2,%3};\n"
        : "+f"(c0), "+f"(c1), "+f"(c2), "+f"(c3)
        : "r"(a0), "r"(a1), "r"(a2), "r"(a3), "r"(b0), "r"(b1));
}

// ------------------------------- routing -----------------------------------
__global__ void init_kernel() {
    if (threadIdx.x < E_EXP) g_cnt[threadIdx.x] = 0;
}

__global__ void gate_kernel(const float* __restrict__ x, const float* __restrict__ wg) {
    int t = blockIdx.x * (blockDim.x >> 5) + (threadIdx.x >> 5);
    int lane = threadIdx.x & 31;
    if (t >= T_TOK) return;
    const float* xr = x + (size_t)t * H_DIM;
    float acc[E_EXP];
#pragma unroll
    for (int e = 0; e < E_EXP; e++) acc[e] = 0.0f;
    for (int h = lane; h < H_DIM; h += 32) {
        float xv = xr[h];
        const float* wr = wg + (size_t)h * E_EXP;
#pragma unroll
        for (int e = 0; e < E_EXP; e++) acc[e] += xv * wr[e];
    }
#pragma unroll
    for (int e = 0; e < E_EXP; e++)
#pragma unroll
        for (int o = 16; o > 0; o >>= 1) acc[e] += __shfl_xor_sync(0xffffffffu, acc[e], o);
    if (lane == 0) {
        int i0 = 0; float v0 = acc[0];
#pragma unroll
        for (int e = 1; e < E_EXP; e++) if (acc[e] > v0) { v0 = acc[e]; i0 = e; }
        int i1 = -1; float v1 = -INFINITY;
#pragma unroll
        for (int e = 0; e < E_EXP; e++) if (e != i0 && acc[e] > v1) { v1 = acc[e]; i1 = e; }
        float w0 = 1.0f / (1.0f + expf(v1 - v0));
        g_te[2 * t] = i0;     g_tw[2 * t] = w0;
        g_te[2 * t + 1] = i1; g_tw[2 * t + 1] = 1.0f - w0;
        atomicAdd(&g_cnt[i0], 1);
        atomicAdd(&g_cnt[i1], 1);
    }
}

__global__ void route_kernel() {
    __shared__ int soff[E_EXP + 1];
    if (threadIdx.x == 0) {
        int o = 0;
#pragma unroll
        for (int e = 0; e < E_EXP; e++) { soff[e] = o; o += (g_cnt[e] + 127) & ~127; }
        soff[E_EXP] = o;
#pragma unroll
        for (int e = 0; e <= E_EXP; e++) g_off[e] = soff[e];
#pragma unroll
        for (int e = 0; e < E_EXP; e++) g_fill[e] = 0;
    }
    __syncthreads();
    if (threadIdx.x < MTILES) {
        int i = threadIdx.x, e = -1;
#pragma unroll
        for (int ee = 0; ee < E_EXP; ee++)
            if (i * 128 >= soff[ee] && i * 128 < soff[ee + 1]) e = ee;
        g_tile_e[i] = e;
    }
    for (int r = threadIdx.x; r < ROWS_CAP; r += blockDim.x) {
        g_rows[r] = 0;
        g_rw[r] = 0.0f;
    }
}

__global__ void scatter_kernel() {
    int t = blockIdx.x * blockDim.x + threadIdx.x;
    if (t >= T_TOK) return;
#pragma unroll
    for (int s = 0; s < 2; s++) {
        int e = g_te[2 * t + s];
        int r = g_off[e] + atomicAdd(&g_fill[e], 1);
        g_rows[r] = t;
        g_rw[r] = g_tw[2 * t + s];
        g_pos[2 * t + s] = r;
    }
}

// gather + rna-round to tf32 (A operand of GEMM1 pre-rounded)
__global__ void gather_kernel(const float* __restrict__ x) {
    int idx = blockIdx.x * blockDim.x + threadIdx.x;
    int r = idx >> 9;                  // 512 float4 per row
    if (r >= g_off[E_EXP]) return;
    int h = (idx & 511) << 2;
    float4 v = *reinterpret_cast<const float4*>(x + (size_t)g_rows[r] * H_DIM + h);
    float4 o = make_float4(__uint_as_float(f2tf(v.x)), __uint_as_float(f2tf(v.y)),
                           __uint_as_float(f2tf(v.z)), __uint_as_float(f2tf(v.w)));
    *reinterpret_cast<float4*>(g_X + (size_t)r * H_DIM + h) = o;
}

// ---------------------------------------------------------------------------
// tf32 GEMM, 128x128x32 tile, 256 thr (4M x 2N warps, warp tile 32x64),
// cp.async 3-stage pipeline, 1 __syncthreads per K-tile, 2 CTAs/SM.
// mode 0: C = g_X @ w1[e];  g_A = silu(C)
// mode 1: C = g_X @ w3[e];  g_A = tf32(g_A * C * rw)
// mode 2: C = g_A @ w2[e];  g_Y = C
// ---------------------------------------------------------------------------
__global__ __launch_bounds__(256, 2) void gemm_kernel(const float* __restrict__ W,
                                                      int K, int lda, int ldb, int mode) {
    extern __shared__ uint32_t smem[];

    const int my = blockIdx.y;
    const int e = g_tile_e[my];
    if (e < 0) return;

    const int tid = threadIdx.x;
    const int warp = tid >> 5;
    const int lane = tid & 31;
    const int wm = warp & 3;
    const int wn = warp >> 2;
    const int g = lane >> 2;
    const int tg = lane & 3;

    const int bm = my * 128;
    const int bn = blockIdx.x * 128;

    const float* Abase = (mode <= 1) ? g_X : g_A;
    const float* Bbase = W + (size_t)e * (size_t)K * (size_t)ldb;
    const uint32_t sbase = smem_u32(smem);

    // per-thread staging sources / dst byte-offsets
    const float* a_src[4];
    const float* b_src[4];
    uint32_t da[4], db[4];
#pragma unroll
    for (int i = 0; i < 4; i++) {
        int slot = tid + i * 256;
        int r = slot >> 3;
        int c4 = (slot & 7) << 2;
        a_src[i] = Abase + (size_t)(bm + r) * lda + c4;
        da[i] = (uint32_t)(r * 36 + c4) * 4u;
    }
#pragma unroll
    for (int i = 0; i < 4; i++) {
        int slot = tid + i * 256;
        int r = slot >> 5;
        int c4 = (slot & 31) << 2;
        b_src[i] = Bbase + (size_t)r * ldb + bn + c4;
        db[i] = (uint32_t)(AS_W + r * 136 + c4) * 4u;
    }

    float c[2][8][4];
#pragma unroll
    for (int mi = 0; mi < 2; mi++)
#pragma unroll
        for (int ni = 0; ni < 8; ni++)
#pragma unroll
            for (int q = 0; q < 4; q++) c[mi][ni][q] = 0.0f;

    const int kt = K / 32;

    // prologue: issue tiles 0 and 1
#pragma unroll
    for (int it = 0; it < 2; it++) {
        uint32_t ab = sbase + (uint32_t)(it % STAGES) * (STG_W * 4);
        int k0 = it * 32;
#pragma unroll
        for (int i = 0; i < 4; i++) cp16(ab + da[i], a_src[i] + k0);
#pragma unroll
        for (int i = 0; i < 4; i++) cp16(ab + db[i], b_src[i] + (size_t)k0 * ldb);
        CP_COMMIT();
    }

    for (int it = 0; it < kt; it++) {
        CP_WAIT1();
        __syncthreads();

        // issue tile it+2 (slot held tile it-1; barrier above ordered its compute)
        if (it + 2 < kt) {
            int nt = it + 2;
            uint32_t ab = sbase + (uint32_t)(nt % STAGES) * (STG_W * 4);
            int k0 = nt * 32;
#pragma unroll
            for (int i = 0; i < 4; i++) cp16(ab + da[i], a_src[i] + k0);
#pragma unroll
            for (int i = 0; i < 4; i++) cp16(ab + db[i], b_src[i] + (size_t)k0 * ldb);
            CP_COMMIT();
        }

        const uint32_t* Asb = smem + (it % STAGES) * STG_W;
        const uint32_t* Bsb = Asb + AS_W;

#pragma unroll
        for (int ks = 0; ks < 4; ks++) {
            const int kk = ks * 8;
            uint32_t a[2][4];
            uint32_t b[8][2];
#pragma unroll
            for (int mi = 0; mi < 2; mi++) {
                int r0 = wm * 32 + mi * 16;
                a[mi][0] = Asb[(r0 + g) * 36 + kk + tg];
                a[mi][1] = Asb[(r0 + 8 + g) * 36 + kk + tg];
                a[mi][2] = Asb[(r0 + g) * 36 + kk + tg + 4];
                a[mi][3] = Asb[(r0 + 8 + g) * 36 + kk + tg + 4];
            }
#pragma unroll
            for (int ni = 0; ni < 8; ni++) {
                int col = wn * 64 + ni * 8 + g;
                // B staged raw f32: rna-round to tf32 here
                b[ni][0] = f2tf(__uint_as_float(Bsb[(kk + tg) * 136 + col]));
                b[ni][1] = f2tf(__uint_as_float(Bsb[(kk + tg + 4) * 136 + col]));
            }
#pragma unroll
            for (int mi = 0; mi < 2; mi++)
#pragma unroll
                for (int ni = 0; ni < 8; ni++)
                    mma_tf32(c[mi][ni][0], c[mi][ni][1], c[mi][ni][2], c[mi][ni][3],
                             a[mi][0], a[mi][1], a[mi][2], a[mi][3],
                             b[ni][0], b[ni][1]);
        }
    }

    // epilogue; c0->(r0,cl), c1->(r0,cl+1), c2->(r0+8,cl), c3->(r0+8,cl+1)
    const int r_base = bm + wm * 32;
    const int c_base = bn + wn * 64;

    if (mode == 0) {
#pragma unroll
        for (int mi = 0; mi < 2; mi++) {
            int r0 = r_base + mi * 16 + g;
            size_t o0 = (size_t)r0 * F_DIM;
            size_t o1 = (size_t)(r0 + 8) * F_DIM;
#pragma unroll
            for (int ni = 0; ni < 8; ni++) {
                int cl = c_base + ni * 8 + 2 * tg;
                *reinterpret_cast<float2*>(g_A + o0 + cl) =
                    make_float2(silu_f(c[mi][ni][0]), silu_f(c[mi][ni][1]));
                *reinterpret_cast<float2*>(g_A + o1 + cl) =
                    make_float2(silu_f(c[mi][ni][2]), silu_f(c[mi][ni][3]));
            }
        }
    } else if (mode == 1) {
#pragma unroll
        for (int mi = 0; mi < 2; mi++) {
            int r0 = r_base + mi * 16 + g;
            float wa = g_rw[r0];
            float wb = g_rw[r0 + 8];
            size_t o0 = (size_t)r0 * F_DIM;
            size_t o1 = (size_t)(r0 + 8) * F_DIM;
#pragma unroll
            for (int ni = 0; ni < 8; ni++) {
                int cl = c_base + ni * 8 + 2 * tg;
                float2 p0 = *reinterpret_cast<const float2*>(g_A + o0 + cl);
                float2 p1 = *reinterpret_cast<const float2*>(g_A + o1 + cl);
                // round final activations to tf32 (A operand of GEMM2)
                p0.x = __uint_as_float(f2tf(p0.x * c[mi][ni][0] * wa));
                p0.y = __uint_as_float(f2tf(p0.y * c[mi][ni][1] * wa));
                p1.x = __uint_as_float(f2tf(p1.x * c[mi][ni][2] * wb));
                p1.y = __uint_as_float(f2tf(p1.y * c[mi][ni][3] * wb));
                *reinterpret_cast<float2*>(g_A + o0 + cl) = p0;
                *reinterpret_cast<float2*>(g_A + o1 + cl) = p1;
            }
        }
    } else {
#pragma unroll
        for (int mi = 0; mi < 2; mi++) {
            int r0 = r_base + mi * 16 + g;
            size_t o0 = (size_t)r0 * H_DIM;
            size_t o1 = (size_t)(r0 + 8) * H_DIM;
#pragma unroll
            for (int ni = 0; ni < 8; ni++) {
                int cl = c_base + ni * 8 + 2 * tg;
                *reinterpret_cast<float2*>(g_Y + o0 + cl) =
                    make_float2(c[mi][ni][0], c[mi][ni][1]);
                *reinterpret_cast<float2*>(g_Y + o1 + cl) =
                    make_float2(c[mi][ni][2], c[mi][ni][3]);
            }
        }
    }
}

__global__ void combine_kernel(float* __restrict__ out) {
    int i = blockIdx.x * blockDim.x + threadIdx.x;
    int t = i >> 9;
    int h = (i & 511) << 2;
    float4 a = *reinterpret_cast<const float4*>(g_Y + (size_t)g_pos[2 * t] * H_DIM + h);
    float4 b = *reinterpret_cast<const float4*>(g_Y + (size_t)g_pos[2 * t + 1] * H_DIM + h);
    *reinterpret_cast<float4*>(out + (size_t)t * H_DIM + h) =
        make_float4(a.x + b.x, a.y + b.y, a.z + b.z, a.w + b.w);
}

extern "C" void kernel_launch(void* const* d_in, const int* in_sizes, int n_in,
                              void* d_out, int out_size) {
    const float* x  = (const float*)d_in[0];
    const float* wg = (const float*)d_in[1];
    const float* w1 = (const float*)d_in[2];
    const float* w3 = (const float*)d_in[3];
    const float* w2 = (const float*)d_in[4];
    float* out = (float*)d_out;

    cudaFuncSetAttribute(gemm_kernel, cudaFuncAttributeMaxDynamicSharedMemorySize, SMEM_BYTES);

    init_kernel<<<1, 32>>>();
    gate_kernel<<<T_TOK / 8, 256>>>(x, wg);
    route_kernel<<<1, 256>>>();
    scatter_kernel<<<T_TOK / 256, 256>>>();
    gather_kernel<<<ROWS_CAP * 512 / 256, 256>>>(x);

    dim3 g1(F_DIM / 128, MTILES);
    gemm_kernel<<<g1, 256, SMEM_BYTES>>>(w1, H_DIM, H_DIM, F_DIM, 0);
    gemm_kernel<<<g1, 256, SMEM_BYTES>>>(w3, H_DIM, H_DIM, F_DIM, 1);

    dim3 g2(H_DIM / 128, MTILES);
    gemm_kernel<<<g2, 256, SMEM_BYTES>>>(w2, F_DIM, F_DIM, H_DIM, 2);

    combine_kernel<<<(T_TOK * H_DIM / 4) / 256, 256>>>(out);
}

// round 6
// speedup vs baseline: 1.6098x; 1.2034x over previous
#include <cuda_runtime.h>
#include <stdint.h>
#include <math.h>

#define T_TOK 1024
#define H_DIM 2048
#define F_DIM 4096
#define E_EXP 8
#define ROWS_CAP 3072
#define MTILES (ROWS_CAP / 128)   // 24

// GEMM1 (fused w1/w3): block 128x64, stages of A(128x32)+B1(32x64)+B3(32x64)
#define AS_W 4608                 // 128*36 words
#define B13_W 2304                // 32*72 words
#define STG13_W (AS_W + 2 * B13_W)
#define SMEM13 (3 * STG13_W * 4)  // 110592 B
// GEMM2: block 128x128
#define B2_W 4352                 // 32*136 words
#define STG2_W (AS_W + B2_W)
#define SMEM2 (3 * STG2_W * 4)    // 107520 B

// ---------------- scratch ----------------
__device__ __align__(256) float g_X[(size_t)ROWS_CAP * H_DIM];
__device__ __align__(256) float g_A[(size_t)ROWS_CAP * F_DIM];
__device__ __align__(256) float g_Y[2 * (size_t)ROWS_CAP * H_DIM];
__device__ int   g_off[E_EXP + 1];
__device__ int   g_tile_e[MTILES];
__device__ int   g_rows[ROWS_CAP];
__device__ float g_rw[ROWS_CAP];
__device__ int   g_pos[T_TOK * 2];
__device__ int   g_te[T_TOK * 2];
__device__ float g_tw[T_TOK * 2];

__device__ __forceinline__ uint32_t f2tf(float f) {
    uint32_t u;
    asm("cvt.rna.tf32.f32 %0, %1;" : "=r"(u) : "f"(f));
    return u;
}
__device__ __forceinline__ float silu_f(float v) { return v / (1.0f + expf(-v)); }

__device__ __forceinline__ uint32_t smem_u32(const void* p) {
    uint32_t a;
    asm("{ .reg .u64 t; cvta.to.shared.u64 t, %1; cvt.u32.u64 %0, t; }" : "=r"(a) : "l"(p));
    return a;
}
__device__ __forceinline__ void cp16(uint32_t dst, const float* src) {
    asm volatile("cp.async.cg.shared.global [%0], [%1], 16;" :: "r"(dst), "l"(src));
}
#define CP_COMMIT() asm volatile("cp.async.commit_group;" ::: "memory")
#define CP_WAIT1()  asm volatile("cp.async.wait_group 1;" ::: "memory")

__device__ __forceinline__ void mma_tf32(float& c0, float& c1, float& c2, float& c3,
                                         uint32_t a0, uint32_t a1, uint32_t a2, uint32_t a3,
                                         uint32_t b0, uint32_t b1) {
    asm volatile(
        "mma.sync.aligned.m16n8k8.row.col.f32.tf32.tf32.f32 "
        "{%0,%1,%2,%3}, {%4,%5,%6,%7}, {%8,%9}, {%0,%1,%2,%3};\n"
        : "+f"(c0), "+f"(c1), "+f"(c2), "+f"(c3)
        : "r"(a0), "r"(a1), "r"(a2), "r"(a3), "r"(b0), "r"(b1));
}

// ------------------------------- routing -----------------------------------
// one warp per token; writes per-slot expert + weight only (no atomics)
__global__ void gate_kernel(const float* __restrict__ x, const float* __restrict__ wg) {
    int t = blockIdx.x * (blockDim.x >> 5) + (threadIdx.x >> 5);
    int lane = threadIdx.x & 31;
    if (t >= T_TOK) return;
    const float* xr = x + (size_t)t * H_DIM;
    float acc[E_EXP];
#pragma unroll
    for (int e = 0; e < E_EXP; e++) acc[e] = 0.0f;
    for (int h = lane; h < H_DIM; h += 32) {
        float xv = xr[h];
        const float* wr = wg + (size_t)h * E_EXP;
#pragma unroll
        for (int e = 0; e < E_EXP; e++) acc[e] += xv * wr[e];
    }
#pragma unroll
    for (int e = 0; e < E_EXP; e++)
#pragma unroll
        for (int o = 16; o > 0; o >>= 1) acc[e] += __shfl_xor_sync(0xffffffffu, acc[e], o);
    if (lane == 0) {
        int i0 = 0; float v0 = acc[0];
#pragma unroll
        for (int e = 1; e < E_EXP; e++) if (acc[e] > v0) { v0 = acc[e]; i0 = e; }
        int i1 = -1; float v1 = -INFINITY;
#pragma unroll
        for (int e = 0; e < E_EXP; e++) if (e != i0 && acc[e] > v1) { v1 = acc[e]; i1 = e; }
        float w0 = 1.0f / (1.0f + expf(v1 - v0));
        g_te[2 * t] = i0;     g_tw[2 * t] = w0;
        g_te[2 * t + 1] = i1; g_tw[2 * t + 1] = 1.0f - w0;
    }
}

// single block: histogram, 128-aligned offsets, tile map, row init, scatter
__global__ void route_scatter_kernel() {
    __shared__ int scnt[E_EXP], soff[E_EXP + 1], sfill[E_EXP];
    int tid = threadIdx.x;
    if (tid < E_EXP) { scnt[tid] = 0; sfill[tid] = 0; }
    __syncthreads();
    for (int i = tid; i < 2 * T_TOK; i += 256) atomicAdd(&scnt[g_te[i]], 1);
    __syncthreads();
    if (tid == 0) {
        int o = 0;
#pragma unroll
        for (int e = 0; e < E_EXP; e++) { soff[e] = o; o += (scnt[e] + 127) & ~127; }
        soff[E_EXP] = o;
#pragma unroll
        for (int e = 0; e <= E_EXP; e++) g_off[e] = soff[e];
    }
    __syncthreads();
    if (tid < MTILES) {
        int e = -1;
#pragma unroll
        for (int ee = 0; ee < E_EXP; ee++)
            if (tid * 128 >= soff[ee] && tid * 128 < soff[ee + 1]) e = ee;
        g_tile_e[tid] = e;
    }
    for (int r = tid; r < ROWS_CAP; r += 256) {
        g_rows[r] = 0;
        g_rw[r] = 0.0f;
    }
    __syncthreads();
    for (int t = tid; t < T_TOK; t += 256) {
#pragma unroll
        for (int s = 0; s < 2; s++) {
            int e = g_te[2 * t + s];
            int r = soff[e] + atomicAdd(&sfill[e], 1);
            g_rows[r] = t;
            g_rw[r] = g_tw[2 * t + s];
            g_pos[2 * t + s] = r;
        }
    }
}

// gather + rna-round (A operand of GEMM1 pre-rounded)
__global__ void gather_kernel(const float* __restrict__ x) {
    int idx = blockIdx.x * blockDim.x + threadIdx.x;
    int r = idx >> 9;
    if (r >= g_off[E_EXP]) return;
    int h = (idx & 511) << 2;
    float4 v = *reinterpret_cast<const float4*>(x + (size_t)g_rows[r] * H_DIM + h);
    *reinterpret_cast<float4*>(g_X + (size_t)r * H_DIM + h) =
        make_float4(__uint_as_float(f2tf(v.x)), __uint_as_float(f2tf(v.y)),
                    __uint_as_float(f2tf(v.z)), __uint_as_float(f2tf(v.w)));
}

// ---------------------------------------------------------------------------
// GEMM1 fused: C1 = g_X@w1[e], C3 = g_X@w3[e]; g_A = tf32(silu(C1)*C3*rw).
// Block 128x64x32, 8 warps (4M x 2N), warp tile 32x32 (2mi x 4ni) x 2 outputs.
// ---------------------------------------------------------------------------
__global__ __launch_bounds__(256, 2) void gemm13_kernel(const float* __restrict__ w1,
                                                        const float* __restrict__ w3) {
    extern __shared__ uint32_t smem[];

    const int my = blockIdx.y;
    const int e = g_tile_e[my];
    if (e < 0) return;

    const int tid = threadIdx.x;
    const int warp = tid >> 5;
    const int lane = tid & 31;
    const int wm = warp & 3;
    const int wn = warp >> 2;
    const int g = lane >> 2;
    const int tg = lane & 3;

    const int bm = my * 128;
    const int bn = blockIdx.x * 64;

    const float* B1 = w1 + (size_t)e * H_DIM * F_DIM;
    const float* B3 = w3 + (size_t)e * H_DIM * F_DIM;
    const uint32_t sbase = smem_u32(smem);

    const float* a_src[4];
    uint32_t da[4];
#pragma unroll
    for (int i = 0; i < 4; i++) {
        int slot = tid + i * 256;
        int r = slot >> 3;
        int c4 = (slot & 7) << 2;
        a_src[i] = g_X + (size_t)(bm + r) * H_DIM + c4;
        da[i] = (uint32_t)(r * 36 + c4) * 4u;
    }
    const float* b1_src[2];
    const float* b3_src[2];
    uint32_t db[2];
#pragma unroll
    for (int i = 0; i < 2; i++) {
        int slot = tid + i * 256;
        int r = slot >> 4;                     // 16 float4 per 64-float row
        int c4 = (slot & 15) << 2;
        b1_src[i] = B1 + (size_t)r * F_DIM + bn + c4;
        b3_src[i] = B3 + (size_t)r * F_DIM + bn + c4;
        db[i] = (uint32_t)(AS_W + r * 72 + c4) * 4u;
    }

    float c1[2][4][4], c3[2][4][4];
#pragma unroll
    for (int mi = 0; mi < 2; mi++)
#pragma unroll
        for (int ni = 0; ni < 4; ni++)
#pragma unroll
            for (int q = 0; q < 4; q++) { c1[mi][ni][q] = 0.0f; c3[mi][ni][q] = 0.0f; }

    const int kt = H_DIM / 32;  // 64

#pragma unroll
    for (int it = 0; it < 2; it++) {
        uint32_t ab = sbase + (uint32_t)it * (STG13_W * 4);
        int k0 = it * 32;
#pragma unroll
        for (int i = 0; i < 4; i++) cp16(ab + da[i], a_src[i] + k0);
#pragma unroll
        for (int i = 0; i < 2; i++) cp16(ab + db[i], b1_src[i] + (size_t)k0 * F_DIM);
#pragma unroll
        for (int i = 0; i < 2; i++) cp16(ab + db[i] + B13_W * 4, b3_src[i] + (size_t)k0 * F_DIM);
        CP_COMMIT();
    }

    for (int it = 0; it < kt; it++) {
        CP_WAIT1();
        __syncthreads();

        if (it + 2 < kt) {
            int nt = it + 2;
            uint32_t ab = sbase + (uint32_t)(nt % 3) * (STG13_W * 4);
            int k0 = nt * 32;
#pragma unroll
            for (int i = 0; i < 4; i++) cp16(ab + da[i], a_src[i] + k0);
#pragma unroll
            for (int i = 0; i < 2; i++) cp16(ab + db[i], b1_src[i] + (size_t)k0 * F_DIM);
#pragma unroll
            for (int i = 0; i < 2; i++) cp16(ab + db[i] + B13_W * 4, b3_src[i] + (size_t)k0 * F_DIM);
            CP_COMMIT();
        }

        const uint32_t* Asb = smem + (it % 3) * STG13_W;
        const uint32_t* Bs1 = Asb + AS_W;
        const uint32_t* Bs3 = Bs1 + B13_W;

#pragma unroll
        for (int ks = 0; ks < 4; ks++) {
            const int kk = ks * 8;
            uint32_t a[2][4];
            uint32_t b1[4][2], b3[4][2];
#pragma unroll
            for (int mi = 0; mi < 2; mi++) {
                int r0 = wm * 32 + mi * 16;
                a[mi][0] = Asb[(r0 + g) * 36 + kk + tg];
                a[mi][1] = Asb[(r0 + 8 + g) * 36 + kk + tg];
                a[mi][2] = Asb[(r0 + g) * 36 + kk + tg + 4];
                a[mi][3] = Asb[(r0 + 8 + g) * 36 + kk + tg + 4];
            }
#pragma unroll
            for (int ni = 0; ni < 4; ni++) {
                int col = wn * 32 + ni * 8 + g;
                b1[ni][0] = f2tf(__uint_as_float(Bs1[(kk + tg) * 72 + col]));
                b1[ni][1] = f2tf(__uint_as_float(Bs1[(kk + tg + 4) * 72 + col]));
                b3[ni][0] = f2tf(__uint_as_float(Bs3[(kk + tg) * 72 + col]));
                b3[ni][1] = f2tf(__uint_as_float(Bs3[(kk + tg + 4) * 72 + col]));
            }
#pragma unroll
            for (int mi = 0; mi < 2; mi++)
#pragma unroll
                for (int ni = 0; ni < 4; ni++) {
                    mma_tf32(c1[mi][ni][0], c1[mi][ni][1], c1[mi][ni][2], c1[mi][ni][3],
                             a[mi][0], a[mi][1], a[mi][2], a[mi][3], b1[ni][0], b1[ni][1]);
                    mma_tf32(c3[mi][ni][0], c3[mi][ni][1], c3[mi][ni][2], c3[mi][ni][3],
                             a[mi][0], a[mi][1], a[mi][2], a[mi][3], b3[ni][0], b3[ni][1]);
                }
        }
    }

    const int r_base = bm + wm * 32;
    const int c_base = bn + wn * 32;
#pragma unroll
    for (int mi = 0; mi < 2; mi++) {
        int r0 = r_base + mi * 16 + g;
        float wa = g_rw[r0];
        float wb = g_rw[r0 + 8];
        size_t o0 = (size_t)r0 * F_DIM;
        size_t o1 = (size_t)(r0 + 8) * F_DIM;
#pragma unroll
        for (int ni = 0; ni < 4; ni++) {
            int cl = c_base + ni * 8 + 2 * tg;
            float2 v0, v1;
            v0.x = __uint_as_float(f2tf(silu_f(c1[mi][ni][0]) * c3[mi][ni][0] * wa));
            v0.y = __uint_as_float(f2tf(silu_f(c1[mi][ni][1]) * c3[mi][ni][1] * wa));
            v1.x = __uint_as_float(f2tf(silu_f(c1[mi][ni][2]) * c3[mi][ni][2] * wb));
            v1.y = __uint_as_float(f2tf(silu_f(c1[mi][ni][3]) * c3[mi][ni][3] * wb));
            *reinterpret_cast<float2*>(g_A + o0 + cl) = v0;
            *reinterpret_cast<float2*>(g_A + o1 + cl) = v1;
        }
    }
}

// ---------------------------------------------------------------------------
// GEMM2: g_Y[z] = g_A(:, z-half) @ w2[e](z-half, :). 128x128x32 tile, K-split 2.
// ---------------------------------------------------------------------------
__global__ __launch_bounds__(256, 2) void gemm2_kernel(const float* __restrict__ w2) {
    extern __shared__ uint32_t smem[];

    const int my = blockIdx.y;
    const int e = g_tile_e[my];
    if (e < 0) return;
    const int z = blockIdx.z;

    const int tid = threadIdx.x;
    const int warp = tid >> 5;
    const int lane = tid & 31;
    const int wm = warp & 3;
    const int wn = warp >> 2;
    const int g = lane >> 2;
    const int tg = lane & 3;

    const int bm = my * 128;
    const int bn = blockIdx.x * 128;

    const float* Abase = g_A + (size_t)z * (F_DIM / 2);
    const float* Bbase = w2 + (size_t)e * F_DIM * H_DIM + (size_t)z * (F_DIM / 2) * H_DIM;
    const uint32_t sbase = smem_u32(smem);

    const float* a_src[4];
    const float* b_src[4];
    uint32_t da[4], db[4];
#pragma unroll
    for (int i = 0; i < 4; i++) {
        int slot = tid + i * 256;
        int r = slot >> 3;
        int c4 = (slot & 7) << 2;
        a_src[i] = Abase + (size_t)(bm + r) * F_DIM + c4;
        da[i] = (uint32_t)(r * 36 + c4) * 4u;
    }
#pragma unroll
    for (int i = 0; i < 4; i++) {
        int slot = tid + i * 256;
        int r = slot >> 5;
        int c4 = (slot & 31) << 2;
        b_src[i] = Bbase + (size_t)r * H_DIM + bn + c4;
        db[i] = (uint32_t)(AS_W + r * 136 + c4) * 4u;
    }

    float c[2][8][4];
#pragma unroll
    for (int mi = 0; mi < 2; mi++)
#pragma unroll
        for (int ni = 0; ni < 8; ni++)
#pragma unroll
            for (int q = 0; q < 4; q++) c[mi][ni][q] = 0.0f;

    const int kt = (F_DIM / 2) / 32;  // 64

#pragma unroll
    for (int it = 0; it < 2; it++) {
        uint32_t ab = sbase + (uint32_t)it * (STG2_W * 4);
        int k0 = it * 32;
#pragma unroll
        for (int i = 0; i < 4; i++) cp16(ab + da[i], a_src[i] + k0);
#pragma unroll
        for (int i = 0; i < 4; i++) cp16(ab + db[i], b_src[i] + (size_t)k0 * H_DIM);
        CP_COMMIT();
    }

    for (int it = 0; it < kt; it++) {
        CP_WAIT1();
        __syncthreads();

        if (it + 2 < kt) {
            int nt = it + 2;
            uint32_t ab = sbase + (uint32_t)(nt % 3) * (STG2_W * 4);
            int k0 = nt * 32;
#pragma unroll
            for (int i = 0; i < 4; i++) cp16(ab + da[i], a_src[i] + k0);
#pragma unroll
            for (int i = 0; i < 4; i++) cp16(ab + db[i], b_src[i] + (size_t)k0 * H_DIM);
            CP_COMMIT();
        }

        const uint32_t* Asb = smem + (it % 3) * STG2_W;
        const uint32_t* Bsb = Asb + AS_W;

#pragma unroll
        for (int ks = 0; ks < 4; ks++) {
            const int kk = ks * 8;
            uint32_t a[2][4];
            uint32_t b[8][2];
#pragma unroll
            for (int mi = 0; mi < 2; mi++) {
                int r0 = wm * 32 + mi * 16;
                a[mi][0] = Asb[(r0 + g) * 36 + kk + tg];
                a[mi][1] = Asb[(r0 + 8 + g) * 36 + kk + tg];
                a[mi][2] = Asb[(r0 + g) * 36 + kk + tg + 4];
                a[mi][3] = Asb[(r0 + 8 + g) * 36 + kk + tg + 4];
            }
#pragma unroll
            for (int ni = 0; ni < 8; ni++) {
                int col = wn * 64 + ni * 8 + g;
                b[ni][0] = f2tf(__uint_as_float(Bsb[(kk + tg) * 136 + col]));
                b[ni][1] = f2tf(__uint_as_float(Bsb[(kk + tg + 4) * 136 + col]));
            }
#pragma unroll
            for (int mi = 0; mi < 2; mi++)
#pragma unroll
                for (int ni = 0; ni < 8; ni++)
                    mma_tf32(c[mi][ni][0], c[mi][ni][1], c[mi][ni][2], c[mi][ni][3],
                             a[mi][0], a[mi][1], a[mi][2], a[mi][3], b[ni][0], b[ni][1]);
        }
    }

    float* Yp = g_Y + (size_t)z * ((size_t)ROWS_CAP * H_DIM);
    const int r_base = bm + wm * 32;
    const int c_base = bn + wn * 64;
#pragma unroll
    for (int mi = 0; mi < 2; mi++) {
        int r0 = r_base + mi * 16 + g;
        size_t o0 = (size_t)r0 * H_DIM;
        size_t o1 = (size_t)(r0 + 8) * H_DIM;
#pragma unroll
        for (int ni = 0; ni < 8; ni++) {
            int cl = c_base + ni * 8 + 2 * tg;
            *reinterpret_cast<float2*>(Yp + o0 + cl) = make_float2(c[mi][ni][0], c[mi][ni][1]);
            *reinterpret_cast<float2*>(Yp + o1 + cl) = make_float2(c[mi][ni][2], c[mi][ni][3]);
        }
    }
}

// out[t] = sum over (slot, kslice) of Y partials — fixed order, deterministic
__global__ void combine_kernel(float* __restrict__ out) {
    int i = blockIdx.x * blockDim.x + threadIdx.x;
    int t = i >> 9;
    int h = (i & 511) << 2;
    size_t r0 = (size_t)g_pos[2 * t] * H_DIM + h;
    size_t r1 = (size_t)g_pos[2 * t + 1] * H_DIM + h;
    const float* Y1 = g_Y + (size_t)ROWS_CAP * H_DIM;
    float4 a = *reinterpret_cast<const float4*>(g_Y + r0);
    float4 b = *reinterpret_cast<const float4*>(Y1 + r0);
    float4 c = *reinterpret_cast<const float4*>(g_Y + r1);
    float4 d = *reinterpret_cast<const float4*>(Y1 + r1);
    *reinterpret_cast<float4*>(out + (size_t)t * H_DIM + h) =
        make_float4((a.x + b.x) + (c.x + d.x), (a.y + b.y) + (c.y + d.y),
                    (a.z + b.z) + (c.z + d.z), (a.w + b.w) + (c.w + d.w));
}

extern "C" void kernel_launch(void* const* d_in, const int* in_sizes, int n_in,
                              void* d_out, int out_size) {
    const float* x  = (const float*)d_in[0];
    const float* wg = (const float*)d_in[1];
    const float* w1 = (const float*)d_in[2];
    const float* w3 = (const float*)d_in[3];
    const float* w2 = (const float*)d_in[4];
    float* out = (float*)d_out;

    cudaFuncSetAttribute(gemm13_kernel, cudaFuncAttributeMaxDynamicSharedMemorySize, SMEM13);
    cudaFuncSetAttribute(gemm2_kernel, cudaFuncAttributeMaxDynamicSharedMemorySize, SMEM2);

    gate_kernel<<<T_TOK / 8, 256>>>(x, wg);
    route_scatter_kernel<<<1, 256>>>();
    gather_kernel<<<ROWS_CAP * 512 / 256, 256>>>(x);

    dim3 g1(F_DIM / 64, MTILES);
    gemm13_kernel<<<g1, 256, SMEM13>>>(w1, w3);

    dim3 g2(H_DIM / 128, MTILES, 2);
    gemm2_kernel<<<g2, 256, SMEM2>>>(w2);

    combine_kernel<<<(T_TOK * H_DIM / 4) / 256, 256>>>(out);
}

// round 7
// speedup vs baseline: 1.6436x; 1.0210x over previous
#include <cuda_runtime.h>
#include <stdint.h>
#include <math.h>

#define T_TOK 1024
#define H_DIM 2048
#define F_DIM 4096
#define E_EXP 8
#define ROWS_CAP 3072
#define MTILES (ROWS_CAP / 128)   // 24

// GEMM1 (fused w1/w3): block 128x64, stages of A(128x32)+B1(32x64)+B3(32x64)
#define AS_W 4608                 // 128*36 words
#define B13_W 2304                // 32*72 words
#define STG13_W (AS_W + 2 * B13_W)
#define SMEM13 (3 * STG13_W * 4)  // 110592 B
// GEMM2: block 128x128
#define B2_W 4352                 // 32*136 words
#define STG2_W (AS_W + B2_W)
#define SMEM2 (3 * STG2_W * 4)    // 107520 B

// ---------------- scratch ----------------
__device__ __align__(256) float g_X[(size_t)ROWS_CAP * H_DIM];
__device__ __align__(256) float g_A[(size_t)ROWS_CAP * F_DIM];
__device__ __align__(256) float g_Y[2 * (size_t)ROWS_CAP * H_DIM];
__device__ int   g_off[E_EXP + 1];
__device__ int   g_tile_e[MTILES];
__device__ int   g_rows[ROWS_CAP];
__device__ float g_rw[ROWS_CAP];
__device__ int   g_pos[T_TOK * 2];
__device__ int   g_te[T_TOK * 2];
__device__ float g_tw[T_TOK * 2];

__device__ __forceinline__ uint32_t f2tf(float f) {
    uint32_t u;
    asm("cvt.rna.tf32.f32 %0, %1;" : "=r"(u) : "f"(f));
    return u;
}
__device__ __forceinline__ float silu_f(float v) { return v / (1.0f + expf(-v)); }

__device__ __forceinline__ uint32_t smem_u32(const void* p) {
    uint32_t a;
    asm("{ .reg .u64 t; cvta.to.shared.u64 t, %1; cvt.u32.u64 %0, t; }" : "=r"(a) : "l"(p));
    return a;
}
__device__ __forceinline__ void cp16(uint32_t dst, const float* src) {
    asm volatile("cp.async.cg.shared.global [%0], [%1], 16;" :: "r"(dst), "l"(src));
}
#define CP_COMMIT() asm volatile("cp.async.commit_group;" ::: "memory")
#define CP_WAIT1()  asm volatile("cp.async.wait_group 1;" ::: "memory")

__device__ __forceinline__ void mma_tf32(float& c0, float& c1, float& c2, float& c3,
                                         uint32_t a0, uint32_t a1, uint32_t a2, uint32_t a3,
                                         uint32_t b0, uint32_t b1) {
    asm volatile(
        "mma.sync.aligned.m16n8k8.row.col.f32.tf32.tf32.f32 "
        "{%0,%1,%2,%3}, {%4,%5,%6,%7}, {%8,%9}, {%0,%1,%2,%3};\n"
        : "+f"(c0), "+f"(c1), "+f"(c2), "+f"(c3)
        : "r"(a0), "r"(a1), "r"(a2), "r"(a3), "r"(b0), "r"(b1));
}

// ------------------------------- routing -----------------------------------
__global__ void gate_kernel(const float* __restrict__ x, const float* __restrict__ wg) {
    int t = blockIdx.x * (blockDim.x >> 5) + (threadIdx.x >> 5);
    int lane = threadIdx.x & 31;
    if (t >= T_TOK) return;
    const float* xr = x + (size_t)t * H_DIM;
    float acc[E_EXP];
#pragma unroll
    for (int e = 0; e < E_EXP; e++) acc[e] = 0.0f;
    for (int h = lane; h < H_DIM; h += 32) {
        float xv = xr[h];
        const float* wr = wg + (size_t)h * E_EXP;
#pragma unroll
        for (int e = 0; e < E_EXP; e++) acc[e] += xv * wr[e];
    }
#pragma unroll
    for (int e = 0; e < E_EXP; e++)
#pragma unroll
        for (int o = 16; o > 0; o >>= 1) acc[e] += __shfl_xor_sync(0xffffffffu, acc[e], o);
    if (lane == 0) {
        int i0 = 0; float v0 = acc[0];
#pragma unroll
        for (int e = 1; e < E_EXP; e++) if (acc[e] > v0) { v0 = acc[e]; i0 = e; }
        int i1 = -1; float v1 = -INFINITY;
#pragma unroll
        for (int e = 0; e < E_EXP; e++) if (e != i0 && acc[e] > v1) { v1 = acc[e]; i1 = e; }
        float w0 = 1.0f / (1.0f + expf(v1 - v0));
        g_te[2 * t] = i0;     g_tw[2 * t] = w0;
        g_te[2 * t + 1] = i1; g_tw[2 * t + 1] = 1.0f - w0;
    }
}

__global__ void route_scatter_kernel() {
    __shared__ int scnt[E_EXP], soff[E_EXP + 1], sfill[E_EXP];
    int tid = threadIdx.x;
    if (tid < E_EXP) { scnt[tid] = 0; sfill[tid] = 0; }
    __syncthreads();
    for (int i = tid; i < 2 * T_TOK; i += 256) atomicAdd(&scnt[g_te[i]], 1);
    __syncthreads();
    if (tid == 0) {
        int o = 0;
#pragma unroll
        for (int e = 0; e < E_EXP; e++) { soff[e] = o; o += (scnt[e] + 127) & ~127; }
        soff[E_EXP] = o;
#pragma unroll
        for (int e = 0; e <= E_EXP; e++) g_off[e] = soff[e];
    }
    __syncthreads();
    if (tid < MTILES) {
        int e = -1;
#pragma unroll
        for (int ee = 0; ee < E_EXP; ee++)
            if (tid * 128 >= soff[ee] && tid * 128 < soff[ee + 1]) e = ee;
        g_tile_e[tid] = e;
    }
    for (int r = tid; r < ROWS_CAP; r += 256) {
        g_rows[r] = 0;
        g_rw[r] = 0.0f;
    }
    __syncthreads();
    for (int t = tid; t < T_TOK; t += 256) {
#pragma unroll
        for (int s = 0; s < 2; s++) {
            int e = g_te[2 * t + s];
            int r = soff[e] + atomicAdd(&sfill[e], 1);
            g_rows[r] = t;
            g_rw[r] = g_tw[2 * t + s];
            g_pos[2 * t + s] = r;
        }
    }
}

__global__ void gather_kernel(const float* __restrict__ x) {
    int idx = blockIdx.x * blockDim.x + threadIdx.x;
    int r = idx >> 9;
    if (r >= g_off[E_EXP]) return;
    int h = (idx & 511) << 2;
    float4 v = *reinterpret_cast<const float4*>(x + (size_t)g_rows[r] * H_DIM + h);
    *reinterpret_cast<float4*>(g_X + (size_t)r * H_DIM + h) =
        make_float4(__uint_as_float(f2tf(v.x)), __uint_as_float(f2tf(v.y)),
                    __uint_as_float(f2tf(v.z)), __uint_as_float(f2tf(v.w)));
}

// ---------------------------------------------------------------------------
// GEMM1 fused: C1 = g_X@w1[e], C3 = g_X@w3[e]; g_A = tf32(silu(C1)*C3*rw).
// Block 128x64x32, 8 warps (4M x 2N), register-pipelined fragments.
// ---------------------------------------------------------------------------
__global__ __launch_bounds__(256, 2) void gemm13_kernel(const float* __restrict__ w1,
                                                        const float* __restrict__ w3) {
    extern __shared__ uint32_t smem[];

    const int my = blockIdx.y;
    const int e = g_tile_e[my];
    if (e < 0) return;

    const int tid = threadIdx.x;
    const int warp = tid >> 5;
    const int lane = tid & 31;
    const int wm = warp & 3;
    const int wn = warp >> 2;
    const int g = lane >> 2;
    const int tg = lane & 3;

    const int bm = my * 128;
    const int bn = blockIdx.x * 64;

    const float* B1g = w1 + (size_t)e * H_DIM * F_DIM;
    const float* B3g = w3 + (size_t)e * H_DIM * F_DIM;
    const uint32_t sbase = smem_u32(smem);

    const float* a_src[4];
    uint32_t da[4];
#pragma unroll
    for (int i = 0; i < 4; i++) {
        int slot = tid + i * 256;
        int r = slot >> 3;
        int c4 = (slot & 7) << 2;
        a_src[i] = g_X + (size_t)(bm + r) * H_DIM + c4;
        da[i] = (uint32_t)(r * 36 + c4) * 4u;
    }
    const float* b1_src[2];
    const float* b3_src[2];
    uint32_t db[2];
#pragma unroll
    for (int i = 0; i < 2; i++) {
        int slot = tid + i * 256;
        int r = slot >> 4;
        int c4 = (slot & 15) << 2;
        b1_src[i] = B1g + (size_t)r * F_DIM + bn + c4;
        b3_src[i] = B3g + (size_t)r * F_DIM + bn + c4;
        db[i] = (uint32_t)(AS_W + r * 72 + c4) * 4u;
    }

    float c1[2][4][4], c3[2][4][4];
#pragma unroll
    for (int mi = 0; mi < 2; mi++)
#pragma unroll
        for (int ni = 0; ni < 4; ni++)
#pragma unroll
            for (int q = 0; q < 4; q++) { c1[mi][ni][q] = 0.0f; c3[mi][ni][q] = 0.0f; }

    const int kt = H_DIM / 32;  // 64

#pragma unroll
    for (int it = 0; it < 2; it++) {
        uint32_t ab = sbase + (uint32_t)it * (STG13_W * 4);
        int k0 = it * 32;
#pragma unroll
        for (int i = 0; i < 4; i++) cp16(ab + da[i], a_src[i] + k0);
#pragma unroll
        for (int i = 0; i < 2; i++) cp16(ab + db[i], b1_src[i] + (size_t)k0 * F_DIM);
#pragma unroll
        for (int i = 0; i < 2; i++) cp16(ab + db[i] + B13_W * 4, b3_src[i] + (size_t)k0 * F_DIM);
        CP_COMMIT();
    }

    // fragment register ping-pong buffers
    uint32_t af[2][2][4];
    uint32_t bf1[2][4][2], bf3[2][4][2];

    for (int it = 0; it < kt; it++) {
        CP_WAIT1();
        __syncthreads();

        if (it + 2 < kt) {
            int nt = it + 2;
            uint32_t ab = sbase + (uint32_t)(nt % 3) * (STG13_W * 4);
            int k0 = nt * 32;
#pragma unroll
            for (int i = 0; i < 4; i++) cp16(ab + da[i], a_src[i] + k0);
#pragma unroll
            for (int i = 0; i < 2; i++) cp16(ab + db[i], b1_src[i] + (size_t)k0 * F_DIM);
#pragma unroll
            for (int i = 0; i < 2; i++) cp16(ab + db[i] + B13_W * 4, b3_src[i] + (size_t)k0 * F_DIM);
            CP_COMMIT();
        }

        const uint32_t* Asb = smem + (it % 3) * STG13_W;
        const uint32_t* Bs1 = Asb + AS_W;
        const uint32_t* Bs3 = Bs1 + B13_W;

        // load ks=0 fragments into buffer 0
#pragma unroll
        for (int mi = 0; mi < 2; mi++) {
            int r0 = wm * 32 + mi * 16;
            af[0][mi][0] = Asb[(r0 + g) * 36 + tg];
            af[0][mi][1] = Asb[(r0 + 8 + g) * 36 + tg];
            af[0][mi][2] = Asb[(r0 + g) * 36 + tg + 4];
            af[0][mi][3] = Asb[(r0 + 8 + g) * 36 + tg + 4];
        }
#pragma unroll
        for (int ni = 0; ni < 4; ni++) {
            int col = wn * 32 + ni * 8 + g;
            bf1[0][ni][0] = Bs1[tg * 72 + col] + 0x1000u;        // rna-bias round
            bf1[0][ni][1] = Bs1[(tg + 4) * 72 + col] + 0x1000u;
            bf3[0][ni][0] = Bs3[tg * 72 + col] + 0x1000u;
            bf3[0][ni][1] = Bs3[(tg + 4) * 72 + col] + 0x1000u;
        }

#pragma unroll
        for (int ks = 0; ks < 4; ks++) {
            const int cb = ks & 1, nb = cb ^ 1;
            if (ks < 3) {
                const int kk = (ks + 1) * 8;
#pragma unroll
                for (int mi = 0; mi < 2; mi++) {
                    int r0 = wm * 32 + mi * 16;
                    af[nb][mi][0] = Asb[(r0 + g) * 36 + kk + tg];
                    af[nb][mi][1] = Asb[(r0 + 8 + g) * 36 + kk + tg];
                    af[nb][mi][2] = Asb[(r0 + g) * 36 + kk + tg + 4];
                    af[nb][mi][3] = Asb[(r0 + 8 + g) * 36 + kk + tg + 4];
                }
#pragma unroll
                for (int ni = 0; ni < 4; ni++) {
                    int col = wn * 32 + ni * 8 + g;
                    bf1[nb][ni][0] = Bs1[(kk + tg) * 72 + col] + 0x1000u;
                    bf1[nb][ni][1] = Bs1[(kk + tg + 4) * 72 + col] + 0x1000u;
                    bf3[nb][ni][0] = Bs3[(kk + tg) * 72 + col] + 0x1000u;
                    bf3[nb][ni][1] = Bs3[(kk + tg + 4) * 72 + col] + 0x1000u;
                }
            }
#pragma unroll
            for (int mi = 0; mi < 2; mi++)
#pragma unroll
                for (int ni = 0; ni < 4; ni++) {
                    mma_tf32(c1[mi][ni][0], c1[mi][ni][1], c1[mi][ni][2], c1[mi][ni][3],
                             af[cb][mi][0], af[cb][mi][1], af[cb][mi][2], af[cb][mi][3],
                             bf1[cb][ni][0], bf1[cb][ni][1]);
                    mma_tf32(c3[mi][ni][0], c3[mi][ni][1], c3[mi][ni][2], c3[mi][ni][3],
                             af[cb][mi][0], af[cb][mi][1], af[cb][mi][2], af[cb][mi][3],
                             bf3[cb][ni][0], bf3[cb][ni][1]);
                }
        }
    }

    const int r_base = bm + wm * 32;
    const int c_base = bn + wn * 32;
#pragma unroll
    for (int mi = 0; mi < 2; mi++) {
        int r0 = r_base + mi * 16 + g;
        float wa = g_rw[r0];
        float wb = g_rw[r0 + 8];
        size_t o0 = (size_t)r0 * F_DIM;
        size_t o1 = (size_t)(r0 + 8) * F_DIM;
#pragma unroll
        for (int ni = 0; ni < 4; ni++) {
            int cl = c_base + ni * 8 + 2 * tg;
            float2 v0, v1;
            v0.x = __uint_as_float(f2tf(silu_f(c1[mi][ni][0]) * c3[mi][ni][0] * wa));
            v0.y = __uint_as_float(f2tf(silu_f(c1[mi][ni][1]) * c3[mi][ni][1] * wa));
            v1.x = __uint_as_float(f2tf(silu_f(c1[mi][ni][2]) * c3[mi][ni][2] * wb));
            v1.y = __uint_as_float(f2tf(silu_f(c1[mi][ni][3]) * c3[mi][ni][3] * wb));
            *reinterpret_cast<float2*>(g_A + o0 + cl) = v0;
            *reinterpret_cast<float2*>(g_A + o1 + cl) = v1;
        }
    }
}

// ---------------------------------------------------------------------------
// GEMM2: g_Y[z] = g_A(:, z-half) @ w2[e](z-half, :). 128x128x32, K-split 2.
// ---------------------------------------------------------------------------
__global__ __launch_bounds__(256, 2) void gemm2_kernel(const float* __restrict__ w2) {
    extern __shared__ uint32_t smem[];

    const int my = blockIdx.y;
    const int e = g_tile_e[my];
    if (e < 0) return;
    const int z = blockIdx.z;

    const int tid = threadIdx.x;
    const int warp = tid >> 5;
    const int lane = tid & 31;
    const int wm = warp & 3;
    const int wn = warp >> 2;
    const int g = lane >> 2;
    const int tg = lane & 3;

    const int bm = my * 128;
    const int bn = blockIdx.x * 128;

    const float* Abase = g_A + (size_t)z * (F_DIM / 2);
    const float* Bbase = w2 + (size_t)e * F_DIM * H_DIM + (size_t)z * (F_DIM / 2) * H_DIM;
    const uint32_t sbase = smem_u32(smem);

    const float* a_src[4];
    const float* b_src[4];
    uint32_t da[4], db[4];
#pragma unroll
    for (int i = 0; i < 4; i++) {
        int slot = tid + i * 256;
        int r = slot >> 3;
        int c4 = (slot & 7) << 2;
        a_src[i] = Abase + (size_t)(bm + r) * F_DIM + c4;
        da[i] = (uint32_t)(r * 36 + c4) * 4u;
    }
#pragma unroll
    for (int i = 0; i < 4; i++) {
        int slot = tid + i * 256;
        int r = slot >> 5;
        int c4 = (slot & 31) << 2;
        b_src[i] = Bbase + (size_t)r * H_DIM + bn + c4;
        db[i] = (uint32_t)(AS_W + r * 136 + c4) * 4u;
    }

    float c[2][8][4];
#pragma unroll
    for (int mi = 0; mi < 2; mi++)
#pragma unroll
        for (int ni = 0; ni < 8; ni++)
#pragma unroll
            for (int q = 0; q < 4; q++) c[mi][ni][q] = 0.0f;

    const int kt = (F_DIM / 2) / 32;  // 64

#pragma unroll
    for (int it = 0; it < 2; it++) {
        uint32_t ab = sbase + (uint32_t)it * (STG2_W * 4);
        int k0 = it * 32;
#pragma unroll
        for (int i = 0; i < 4; i++) cp16(ab + da[i], a_src[i] + k0);
#pragma unroll
        for (int i = 0; i < 4; i++) cp16(ab + db[i], b_src[i] + (size_t)k0 * H_DIM);
        CP_COMMIT();
    }

    uint32_t af[2][2][4];
    uint32_t bf[2][8][2];

    for (int it = 0; it < kt; it++) {
        CP_WAIT1();
        __syncthreads();

        if (it + 2 < kt) {
            int nt = it + 2;
            uint32_t ab = sbase + (uint32_t)(nt % 3) * (STG2_W * 4);
            int k0 = nt * 32;
#pragma unroll
            for (int i = 0; i < 4; i++) cp16(ab + da[i], a_src[i] + k0);
#pragma unroll
            for (int i = 0; i < 4; i++) cp16(ab + db[i], b_src[i] + (size_t)k0 * H_DIM);
            CP_COMMIT();
        }

        const uint32_t* Asb = smem + (it % 3) * STG2_W;
        const uint32_t* Bsb = Asb + AS_W;

#pragma unroll
        for (int mi = 0; mi < 2; mi++) {
            int r0 = wm * 32 + mi * 16;
            af[0][mi][0] = Asb[(r0 + g) * 36 + tg];
            af[0][mi][1] = Asb[(r0 + 8 + g) * 36 + tg];
            af[0][mi][2] = Asb[(r0 + g) * 36 + tg + 4];
            af[0][mi][3] = Asb[(r0 + 8 + g) * 36 + tg + 4];
        }
#pragma unroll
        for (int ni = 0; ni < 8; ni++) {
            int col = wn * 64 + ni * 8 + g;
            bf[0][ni][0] = Bsb[tg * 136 + col] + 0x1000u;
            bf[0][ni][1] = Bsb[(tg + 4) * 136 + col] + 0x1000u;
        }

#pragma unroll
        for (int ks = 0; ks < 4; ks++) {
            const int cb = ks & 1, nb = cb ^ 1;
            if (ks < 3) {
                const int kk = (ks + 1) * 8;
#pragma unroll
                for (int mi = 0; mi < 2; mi++) {
                    int r0 = wm * 32 + mi * 16;
                    af[nb][mi][0] = Asb[(r0 + g) * 36 + kk + tg];
                    af[nb][mi][1] = Asb[(r0 + 8 + g) * 36 + kk + tg];
                    af[nb][mi][2] = Asb[(r0 + g) * 36 + kk + tg + 4];
                    af[nb][mi][3] = Asb[(r0 + 8 + g) * 36 + kk + tg + 4];
                }
#pragma unroll
                for (int ni = 0; ni < 8; ni++) {
                    int col = wn * 64 + ni * 8 + g;
                    bf[nb][ni][0] = Bsb[(kk + tg) * 136 + col] + 0x1000u;
                    bf[nb][ni][1] = Bsb[(kk + tg + 4) * 136 + col] + 0x1000u;
                }
            }
#pragma unroll
            for (int mi = 0; mi < 2; mi++)
#pragma unroll
                for (int ni = 0; ni < 8; ni++)
                    mma_tf32(c[mi][ni][0], c[mi][ni][1], c[mi][ni][2], c[mi][ni][3],
                             af[cb][mi][0], af[cb][mi][1], af[cb][mi][2], af[cb][mi][3],
                             bf[cb][ni][0], bf[cb][ni][1]);
        }
    }

    float* Yp = g_Y + (size_t)z * ((size_t)ROWS_CAP * H_DIM);
    const int r_base = bm + wm * 32;
    const int c_base = bn + wn * 64;
#pragma unroll
    for (int mi = 0; mi < 2; mi++) {
        int r0 = r_base + mi * 16 + g;
        size_t o0 = (size_t)r0 * H_DIM;
        size_t o1 = (size_t)(r0 + 8) * H_DIM;
#pragma unroll
        for (int ni = 0; ni < 8; ni++) {
            int cl = c_base + ni * 8 + 2 * tg;
            *reinterpret_cast<float2*>(Yp + o0 + cl) = make_float2(c[mi][ni][0], c[mi][ni][1]);
            *reinterpret_cast<float2*>(Yp + o1 + cl) = make_float2(c[mi][ni][2], c[mi][ni][3]);
        }
    }
}

__global__ void combine_kernel(float* __restrict__ out) {
    int i = blockIdx.x * blockDim.x + threadIdx.x;
    int t = i >> 9;
    int h = (i & 511) << 2;
    size_t r0 = (size_t)g_pos[2 * t] * H_DIM + h;
    size_t r1 = (size_t)g_pos[2 * t + 1] * H_DIM + h;
    const float* Y1 = g_Y + (size_t)ROWS_CAP * H_DIM;
    float4 a = *reinterpret_cast<const float4*>(g_Y + r0);
    float4 b = *reinterpret_cast<const float4*>(Y1 + r0);
    float4 c = *reinterpret_cast<const float4*>(g_Y + r1);
    float4 d = *reinterpret_cast<const float4*>(Y1 + r1);
    *reinterpret_cast<float4*>(out + (size_t)t * H_DIM + h) =
        make_float4((a.x + b.x) + (c.x + d.x), (a.y + b.y) + (c.y + d.y),
                    (a.z + b.z) + (c.z + d.z), (a.w + b.w) + (c.w + d.w));
}

extern "C" void kernel_launch(void* const* d_in, const int* in_sizes, int n_in,
                              void* d_out, int out_size) {
    const float* x  = (const float*)d_in[0];
    const float* wg = (const float*)d_in[1];
    const float* w1 = (const float*)d_in[2];
    const float* w3 = (const float*)d_in[3];
    const float* w2 = (const float*)d_in[4];
    float* out = (float*)d_out;

    cudaFuncSetAttribute(gemm13_kernel, cudaFuncAttributeMaxDynamicSharedMemorySize, SMEM13);
    cudaFuncSetAttribute(gemm2_kernel, cudaFuncAttributeMaxDynamicSharedMemorySize, SMEM2);

    gate_kernel<<<T_TOK / 8, 256>>>(x, wg);
    route_scatter_kernel<<<1, 256>>>();
    gather_kernel<<<ROWS_CAP * 512 / 256, 256>>>(x);

    dim3 g1(F_DIM / 64, MTILES);
    gemm13_kernel<<<g1, 256, SMEM13>>>(w1, w3);

    dim3 g2(H_DIM / 128, MTILES, 2);
    gemm2_kernel<<<g2, 256, SMEM2>>>(w2);

    combine_kernel<<<(T_TOK * H_DIM / 4) / 256, 256>>>(out);
}

// round 8
// speedup vs baseline: 2.2995x; 1.3991x over previous
#include <cuda_runtime.h>
#include <cuda_fp16.h>
#include <stdint.h>
#include <math.h>

#define T_TOK 1024
#define H_DIM 2048
#define F_DIM 4096
#define E_EXP 8
#define ROWS_CAP 3072
#define MTILES (ROWS_CAP / 128)   // 24
#define KSPLIT 4

// A tiles: fp16, 128 rows x 32 halves, padded to 40 halves (20 words) per row
#define AP_W 20
#define AS_W (128 * AP_W)         // 2560 words
// GEMM1 B tiles: f32, 32 rows x 64, padded to 68 words
#define BP13 68
#define B13_W (32 * BP13)         // 2176 words
#define STG13_W (AS_W + 2 * B13_W)
#define SMEM13 (3 * STG13_W * 4)  // 82944 B
// GEMM2 B tiles: f32, 32 rows x 128, padded to 132 words
#define BP2 132
#define B2_W (32 * BP2)           // 4224 words
#define STG2_W (AS_W + B2_W)
#define SMEM2 (3 * STG2_W * 4)    // 81408 B

// ---------------- scratch ----------------
__device__ __align__(256) __half g_X[(size_t)ROWS_CAP * H_DIM];
__device__ __align__(256) __half g_A[(size_t)ROWS_CAP * F_DIM];
__device__ __align__(256) float  g_Y[(size_t)KSPLIT * ROWS_CAP * H_DIM];
__device__ int   g_off[E_EXP + 1];
__device__ int   g_tile_e[MTILES];
__device__ int   g_rows[ROWS_CAP];
__device__ float g_rw[ROWS_CAP];
__device__ int   g_pos[T_TOK * 2];
__device__ int   g_te[T_TOK * 2];
__device__ float g_tw[T_TOK * 2];

__device__ __forceinline__ float silu_f(float v) { return v / (1.0f + expf(-v)); }

__device__ __forceinline__ uint32_t smem_u32(const void* p) {
    uint32_t a;
    asm("{ .reg .u64 t; cvta.to.shared.u64 t, %1; cvt.u32.u64 %0, t; }" : "=r"(a) : "l"(p));
    return a;
}
__device__ __forceinline__ void cp16(uint32_t dst, const void* src) {
    asm volatile("cp.async.cg.shared.global [%0], [%1], 16;" :: "r"(dst), "l"(src));
}
#define CP_COMMIT() asm volatile("cp.async.commit_group;" ::: "memory")
#define CP_WAIT1()  asm volatile("cp.async.wait_group 1;" ::: "memory")

// pack two f32 -> half2 reg: lo = first arg, hi = second (PTX src1 = high half)
__device__ __forceinline__ uint32_t pack_h2(float lo, float hi) {
    uint32_t d;
    asm("cvt.rn.f16x2.f32 %0, %1, %2;" : "=r"(d) : "f"(hi), "f"(lo));
    return d;
}

__device__ __forceinline__ void mma_f16(float& c0, float& c1, float& c2, float& c3,
                                        uint32_t a0, uint32_t a1, uint32_t a2, uint32_t a3,
                                        uint32_t b0, uint32_t b1) {
    asm volatile(
        "mma.sync.aligned.m16n8k16.row.col.f32.f16.f16.f32 "
        "{%0,%1,%2,%3}, {%4,%5,%6,%7}, {%8,%9}, {%0,%1,%2,%3};\n"
        : "+f"(c0), "+f"(c1), "+f"(c2), "+f"(c3)
        : "r"(a0), "r"(a1), "r"(a2), "r"(a3), "r"(b0), "r"(b1));
}

// ------------------------------- routing -----------------------------------
__global__ void gate_kernel(const float* __restrict__ x, const float* __restrict__ wg) {
    int t = blockIdx.x * (blockDim.x >> 5) + (threadIdx.x >> 5);
    int lane = threadIdx.x & 31;
    if (t >= T_TOK) return;
    const float* xr = x + (size_t)t * H_DIM;
    float acc[E_EXP];
#pragma unroll
    for (int e = 0; e < E_EXP; e++) acc[e] = 0.0f;
    for (int h = lane; h < H_DIM; h += 32) {
        float xv = xr[h];
        const float* wr = wg + (size_t)h * E_EXP;
#pragma unroll
        for (int e = 0; e < E_EXP; e++) acc[e] += xv * wr[e];
    }
#pragma unroll
    for (int e = 0; e < E_EXP; e++)
#pragma unroll
        for (int o = 16; o > 0; o >>= 1) acc[e] += __shfl_xor_sync(0xffffffffu, acc[e], o);
    if (lane == 0) {
        int i0 = 0; float v0 = acc[0];
#pragma unroll
        for (int e = 1; e < E_EXP; e++) if (acc[e] > v0) { v0 = acc[e]; i0 = e; }
        int i1 = -1; float v1 = -INFINITY;
#pragma unroll
        for (int e = 0; e < E_EXP; e++) if (e != i0 && acc[e] > v1) { v1 = acc[e]; i1 = e; }
        float w0 = 1.0f / (1.0f + expf(v1 - v0));
        g_te[2 * t] = i0;     g_tw[2 * t] = w0;
        g_te[2 * t + 1] = i1; g_tw[2 * t + 1] = 1.0f - w0;
    }
}

__global__ void route_scatter_kernel() {
    __shared__ int scnt[E_EXP], soff[E_EXP + 1], sfill[E_EXP];
    int tid = threadIdx.x;
    if (tid < E_EXP) { scnt[tid] = 0; sfill[tid] = 0; }
    __syncthreads();
    for (int i = tid; i < 2 * T_TOK; i += 256) atomicAdd(&scnt[g_te[i]], 1);
    __syncthreads();
    if (tid == 0) {
        int o = 0;
#pragma unroll
        for (int e = 0; e < E_EXP; e++) { soff[e] = o; o += (scnt[e] + 127) & ~127; }
        soff[E_EXP] = o;
#pragma unroll
        for (int e = 0; e <= E_EXP; e++) g_off[e] = soff[e];
    }
    __syncthreads();
    if (tid < MTILES) {
        int e = -1;
#pragma unroll
        for (int ee = 0; ee < E_EXP; ee++)
            if (tid * 128 >= soff[ee] && tid * 128 < soff[ee + 1]) e = ee;
        g_tile_e[tid] = e;
    }
    for (int r = tid; r < ROWS_CAP; r += 256) {
        g_rows[r] = 0;
        g_rw[r] = 0.0f;
    }
    __syncthreads();
    for (int t = tid; t < T_TOK; t += 256) {
#pragma unroll
        for (int s = 0; s < 2; s++) {
            int e = g_te[2 * t + s];
            int r = soff[e] + atomicAdd(&sfill[e], 1);
            g_rows[r] = t;
            g_rw[r] = g_tw[2 * t + s];
            g_pos[2 * t + s] = r;
        }
    }
}

// gather x rows -> fp16 g_X
__global__ void gather_kernel(const float* __restrict__ x) {
    int idx = blockIdx.x * blockDim.x + threadIdx.x;
    int r = idx >> 9;                 // 512 quads per row
    if (r >= g_off[E_EXP]) return;
    int h = (idx & 511) << 2;
    float4 v = *reinterpret_cast<const float4*>(x + (size_t)g_rows[r] * H_DIM + h);
    __half2 h0 = __floats2half2_rn(v.x, v.y);
    __half2 h1 = __floats2half2_rn(v.z, v.w);
    *reinterpret_cast<__half2*>(g_X + (size_t)r * H_DIM + h) = h0;
    *reinterpret_cast<__half2*>(g_X + (size_t)r * H_DIM + h + 2) = h1;
}

// ---------------------------------------------------------------------------
// GEMM1 fused (fp16 mma): C1 = g_X@w1[e], C3 = g_X@w3[e];
// g_A = fp16(silu(C1)*C3*rw). Block 128x64x32, 8 warps (4M x 2N).
// ---------------------------------------------------------------------------
__global__ __launch_bounds__(256, 2) void gemm13_kernel(const float* __restrict__ w1,
                                                        const float* __restrict__ w3) {
    extern __shared__ uint32_t smem[];

    const int my = blockIdx.y;
    const int e = g_tile_e[my];
    if (e < 0) return;

    const int tid = threadIdx.x;
    const int warp = tid >> 5;
    const int lane = tid & 31;
    const int wm = warp & 3;
    const int wn = warp >> 2;
    const int g = lane >> 2;
    const int tg = lane & 3;

    const int bm = my * 128;
    const int bn = blockIdx.x * 64;

    const float* B1g = w1 + (size_t)e * H_DIM * F_DIM;
    const float* B3g = w3 + (size_t)e * H_DIM * F_DIM;
    const uint32_t sbase = smem_u32(smem);

    // A staging: 512 16B slots (128 rows x 4), 2 per thread
    const __half* a_src[2];
    uint32_t da[2];
#pragma unroll
    for (int i = 0; i < 2; i++) {
        int slot = tid + i * 256;
        int r = slot >> 2;
        int q = slot & 3;
        a_src[i] = g_X + (size_t)(bm + r) * H_DIM + q * 8;
        da[i] = (uint32_t)(r * AP_W * 4 + q * 16);
    }
    // B staging: 512 slots each (32 rows x 16 quads), 2 per thread
    const float* b1_src[2];
    const float* b3_src[2];
    uint32_t db[2];
#pragma unroll
    for (int i = 0; i < 2; i++) {
        int slot = tid + i * 256;
        int r = slot >> 4;
        int c4 = (slot & 15) << 2;
        b1_src[i] = B1g + (size_t)r * F_DIM + bn + c4;
        b3_src[i] = B3g + (size_t)r * F_DIM + bn + c4;
        db[i] = (uint32_t)(AS_W + r * BP13 + c4) * 4u;
    }

    float c1[2][4][4], c3[2][4][4];
#pragma unroll
    for (int mi = 0; mi < 2; mi++)
#pragma unroll
        for (int ni = 0; ni < 4; ni++)
#pragma unroll
            for (int q = 0; q < 4; q++) { c1[mi][ni][q] = 0.0f; c3[mi][ni][q] = 0.0f; }

    const int kt = H_DIM / 32;  // 64

#pragma unroll
    for (int it = 0; it < 2; it++) {
        uint32_t ab = sbase + (uint32_t)it * (STG13_W * 4);
        int k0 = it * 32;
#pragma unroll
        for (int i = 0; i < 2; i++) cp16(ab + da[i], a_src[i] + k0);
#pragma unroll
        for (int i = 0; i < 2; i++) cp16(ab + db[i], b1_src[i] + (size_t)k0 * F_DIM);
#pragma unroll
        for (int i = 0; i < 2; i++) cp16(ab + db[i] + B13_W * 4, b3_src[i] + (size_t)k0 * F_DIM);
        CP_COMMIT();
    }

    uint32_t af[2][2][4];
    uint32_t bf1[2][4][2], bf3[2][4][2];

    for (int it = 0; it < kt; it++) {
        CP_WAIT1();
        __syncthreads();

        if (it + 2 < kt) {
            int nt = it + 2;
            uint32_t ab = sbase + (uint32_t)(nt % 3) * (STG13_W * 4);
            int k0 = nt * 32;
#pragma unroll
            for (int i = 0; i < 2; i++) cp16(ab + da[i], a_src[i] + k0);
#pragma unroll
            for (int i = 0; i < 2; i++) cp16(ab + db[i], b1_src[i] + (size_t)k0 * F_DIM);
#pragma unroll
            for (int i = 0; i < 2; i++) cp16(ab + db[i] + B13_W * 4, b3_src[i] + (size_t)k0 * F_DIM);
            CP_COMMIT();
        }

        const uint32_t* Asb = smem + (it % 3) * STG13_W;
        const float* Bs1 = (const float*)(Asb + AS_W);
        const float* Bs3 = Bs1 + B13_W;

        // ks=0 fragments -> buffer 0
#pragma unroll
        for (int mi = 0; mi < 2; mi++) {
            int ra = wm * 32 + mi * 16 + g;
            af[0][mi][0] = Asb[ra * AP_W + tg];
            af[0][mi][1] = Asb[(ra + 8) * AP_W + tg];
            af[0][mi][2] = Asb[ra * AP_W + tg + 4];
            af[0][mi][3] = Asb[(ra + 8) * AP_W + tg + 4];
        }
        {
            int rb = 2 * tg;
#pragma unroll
            for (int ni = 0; ni < 4; ni++) {
                int col = wn * 32 + ni * 8 + g;
                bf1[0][ni][0] = pack_h2(Bs1[rb * BP13 + col], Bs1[(rb + 1) * BP13 + col]);
                bf1[0][ni][1] = pack_h2(Bs1[(rb + 8) * BP13 + col], Bs1[(rb + 9) * BP13 + col]);
                bf3[0][ni][0] = pack_h2(Bs3[rb * BP13 + col], Bs3[(rb + 1) * BP13 + col]);
                bf3[0][ni][1] = pack_h2(Bs3[(rb + 8) * BP13 + col], Bs3[(rb + 9) * BP13 + col]);
            }
        }

#pragma unroll
        for (int ks = 0; ks < 2; ks++) {
            const int cb = ks & 1, nb = cb ^ 1;
            if (ks < 1) {
                const int kw = 8;       // A word offset for ks=1
                const int rb = 16 + 2 * tg;
#pragma unroll
                for (int mi = 0; mi < 2; mi++) {
                    int ra = wm * 32 + mi * 16 + g;
                    af[nb][mi][0] = Asb[ra * AP_W + kw + tg];
                    af[nb][mi][1] = Asb[(ra + 8) * AP_W + kw + tg];
                    af[nb][mi][2] = Asb[ra * AP_W + kw + tg + 4];
                    af[nb][mi][3] = Asb[(ra + 8) * AP_W + kw + tg + 4];
                }
#pragma unroll
                for (int ni = 0; ni < 4; ni++) {
                    int col = wn * 32 + ni * 8 + g;
                    bf1[nb][ni][0] = pack_h2(Bs1[rb * BP13 + col], Bs1[(rb + 1) * BP13 + col]);
                    bf1[nb][ni][1] = pack_h2(Bs1[(rb + 8) * BP13 + col], Bs1[(rb + 9) * BP13 + col]);
                    bf3[nb][ni][0] = pack_h2(Bs3[rb * BP13 + col], Bs3[(rb + 1) * BP13 + col]);
                    bf3[nb][ni][1] = pack_h2(Bs3[(rb + 8) * BP13 + col], Bs3[(rb + 9) * BP13 + col]);
                }
            }
#pragma unroll
            for (int mi = 0; mi < 2; mi++)
#pragma unroll
                for (int ni = 0; ni < 4; ni++) {
                    mma_f16(c1[mi][ni][0], c1[mi][ni][1], c1[mi][ni][2], c1[mi][ni][3],
                            af[cb][mi][0], af[cb][mi][1], af[cb][mi][2], af[cb][mi][3],
                            bf1[cb][ni][0], bf1[cb][ni][1]);
                    mma_f16(c3[mi][ni][0], c3[mi][ni][1], c3[mi][ni][2], c3[mi][ni][3],
                            af[cb][mi][0], af[cb][mi][1], af[cb][mi][2], af[cb][mi][3],
                            bf3[cb][ni][0], bf3[cb][ni][1]);
                }
        }
    }

    const int r_base = bm + wm * 32;
    const int c_base = bn + wn * 32;
#pragma unroll
    for (int mi = 0; mi < 2; mi++) {
        int r0 = r_base + mi * 16 + g;
        float wa = g_rw[r0];
        float wb = g_rw[r0 + 8];
        size_t o0 = (size_t)r0 * F_DIM;
        size_t o1 = (size_t)(r0 + 8) * F_DIM;
#pragma unroll
        for (int ni = 0; ni < 4; ni++) {
            int cl = c_base + ni * 8 + 2 * tg;
            __half2 v0 = __floats2half2_rn(silu_f(c1[mi][ni][0]) * c3[mi][ni][0] * wa,
                                           silu_f(c1[mi][ni][1]) * c3[mi][ni][1] * wa);
            __half2 v1 = __floats2half2_rn(silu_f(c1[mi][ni][2]) * c3[mi][ni][2] * wb,
                                           silu_f(c1[mi][ni][3]) * c3[mi][ni][3] * wb);
            *reinterpret_cast<__half2*>(g_A + o0 + cl) = v0;
            *reinterpret_cast<__half2*>(g_A + o1 + cl) = v1;
        }
    }
}

// ---------------------------------------------------------------------------
// GEMM2 (fp16 mma): g_Y[z] = g_A(:, z-quarter) @ w2[e](z-quarter, :).
// Block 128x128x32, K-split 4.
// ---------------------------------------------------------------------------
__global__ __launch_bounds__(256, 2) void gemm2_kernel(const float* __restrict__ w2) {
    extern __shared__ uint32_t smem[];

    const int my = blockIdx.y;
    const int e = g_tile_e[my];
    if (e < 0) return;
    const int z = blockIdx.z;

    const int tid = threadIdx.x;
    const int warp = tid >> 5;
    const int lane = tid & 31;
    const int wm = warp & 3;
    const int wn = warp >> 2;
    const int g = lane >> 2;
    const int tg = lane & 3;

    const int bm = my * 128;
    const int bn = blockIdx.x * 128;
    const int kseg = F_DIM / KSPLIT;   // 1024

    const __half* Abase = g_A + (size_t)z * kseg;
    const float* Bbase = w2 + (size_t)e * F_DIM * H_DIM + (size_t)z * kseg * H_DIM;
    const uint32_t sbase = smem_u32(smem);

    const __half* a_src[2];
    uint32_t da[2];
#pragma unroll
    for (int i = 0; i < 2; i++) {
        int slot = tid + i * 256;
        int r = slot >> 2;
        int q = slot & 3;
        a_src[i] = Abase + (size_t)(bm + r) * F_DIM + q * 8;
        da[i] = (uint32_t)(r * AP_W * 4 + q * 16);
    }
    const float* b_src[4];
    uint32_t db[4];
#pragma unroll
    for (int i = 0; i < 4; i++) {
        int slot = tid + i * 256;
        int r = slot >> 5;
        int c4 = (slot & 31) << 2;
        b_src[i] = Bbase + (size_t)r * H_DIM + bn + c4;
        db[i] = (uint32_t)(AS_W + r * BP2 + c4) * 4u;
    }

    float c[2][8][4];
#pragma unroll
    for (int mi = 0; mi < 2; mi++)
#pragma unroll
        for (int ni = 0; ni < 8; ni++)
#pragma unroll
            for (int q = 0; q < 4; q++) c[mi][ni][q] = 0.0f;

    const int kt = kseg / 32;   // 32

#pragma unroll
    for (int it = 0; it < 2; it++) {
        uint32_t ab = sbase + (uint32_t)it * (STG2_W * 4);
        int k0 = it * 32;
#pragma unroll
        for (int i = 0; i < 2; i++) cp16(ab + da[i], a_src[i] + k0);
#pragma unroll
        for (int i = 0; i < 4; i++) cp16(ab + db[i], b_src[i] + (size_t)k0 * H_DIM);
        CP_COMMIT();
    }

    uint32_t af[2][2][4];
    uint32_t bf[2][8][2];

    for (int it = 0; it < kt; it++) {
        CP_WAIT1();
        __syncthreads();

        if (it + 2 < kt) {
            int nt = it + 2;
            uint32_t ab = sbase + (uint32_t)(nt % 3) * (STG2_W * 4);
            int k0 = nt * 32;
#pragma unroll
            for (int i = 0; i < 2; i++) cp16(ab + da[i], a_src[i] + k0);
#pragma unroll
            for (int i = 0; i < 4; i++) cp16(ab + db[i], b_src[i] + (size_t)k0 * H_DIM);
            CP_COMMIT();
        }

        const uint32_t* Asb = smem + (it % 3) * STG2_W;
        const float* Bsb = (const float*)(Asb + AS_W);

#pragma unroll
        for (int mi = 0; mi < 2; mi++) {
            int ra = wm * 32 + mi * 16 + g;
            af[0][mi][0] = Asb[ra * AP_W + tg];
            af[0][mi][1] = Asb[(ra + 8) * AP_W + tg];
            af[0][mi][2] = Asb[ra * AP_W + tg + 4];
            af[0][mi][3] = Asb[(ra + 8) * AP_W + tg + 4];
        }
        {
            int rb = 2 * tg;
#pragma unroll
            for (int ni = 0; ni < 8; ni++) {
                int col = wn * 64 + ni * 8 + g;
                bf[0][ni][0] = pack_h2(Bsb[rb * BP2 + col], Bsb[(rb + 1) * BP2 + col]);
                bf[0][ni][1] = pack_h2(Bsb[(rb + 8) * BP2 + col], Bsb[(rb + 9) * BP2 + col]);
            }
        }

#pragma unroll
        for (int ks = 0; ks < 2; ks++) {
            const int cb = ks & 1, nb = cb ^ 1;
            if (ks < 1) {
                const int kw = 8;
                const int rb = 16 + 2 * tg;
#pragma unroll
                for (int mi = 0; mi < 2; mi++) {
                    int ra = wm * 32 + mi * 16 + g;
                    af[nb][mi][0] = Asb[ra * AP_W + kw + tg];
                    af[nb][mi][1] = Asb[(ra + 8) * AP_W + kw + tg];
                    af[nb][mi][2] = Asb[ra * AP_W + kw + tg + 4];
                    af[nb][mi][3] = Asb[(ra + 8) * AP_W + kw + tg + 4];
                }
#pragma unroll
                for (int ni = 0; ni < 8; ni++) {
                    int col = wn * 64 + ni * 8 + g;
                    bf[nb][ni][0] = pack_h2(Bsb[rb * BP2 + col], Bsb[(rb + 1) * BP2 + col]);
                    bf[nb][ni][1] = pack_h2(Bsb[(rb + 8) * BP2 + col], Bsb[(rb + 9) * BP2 + col]);
                }
            }
#pragma unroll
            for (int mi = 0; mi < 2; mi++)
#pragma unroll
                for (int ni = 0; ni < 8; ni++)
                    mma_f16(c[mi][ni][0], c[mi][ni][1], c[mi][ni][2], c[mi][ni][3],
                            af[cb][mi][0], af[cb][mi][1], af[cb][mi][2], af[cb][mi][3],
                            bf[cb][ni][0], bf[cb][ni][1]);
        }
    }

    float* Yp = g_Y + (size_t)z * ((size_t)ROWS_CAP * H_DIM);
    const int r_base = bm + wm * 32;
    const int c_base = bn + wn * 64;
#pragma unroll
    for (int mi = 0; mi < 2; mi++) {
        int r0 = r_base + mi * 16 + g;
        size_t o0 = (size_t)r0 * H_DIM;
        size_t o1 = (size_t)(r0 + 8) * H_DIM;
#pragma unroll
        for (int ni = 0; ni < 8; ni++) {
            int cl = c_base + ni * 8 + 2 * tg;
            *reinterpret_cast<float2*>(Yp + o0 + cl) = make_float2(c[mi][ni][0], c[mi][ni][1]);
            *reinterpret_cast<float2*>(Yp + o1 + cl) = make_float2(c[mi][ni][2], c[mi][ni][3]);
        }
    }
}

// out[t] = sum over (slot, kslice) — fixed order, deterministic
__global__ void combine_kernel(float* __restrict__ out) {
    int i = blockIdx.x * blockDim.x + threadIdx.x;
    int t = i >> 9;
    int h = (i & 511) << 2;
    size_t r0 = (size_t)g_pos[2 * t] * H_DIM + h;
    size_t r1 = (size_t)g_pos[2 * t + 1] * H_DIM + h;
    const size_t SL = (size_t)ROWS_CAP * H_DIM;
    float4 s0 = make_float4(0.f, 0.f, 0.f, 0.f);
    float4 s1 = make_float4(0.f, 0.f, 0.f, 0.f);
#pragma unroll
    for (int z = 0; z < KSPLIT; z++) {
        float4 a = *reinterpret_cast<const float4*>(g_Y + z * SL + r0);
        float4 b = *reinterpret_cast<const float4*>(g_Y + z * SL + r1);
        s0.x += a.x; s0.y += a.y; s0.z += a.z; s0.w += a.w;
        s1.x += b.x; s1.y += b.y; s1.z += b.z; s1.w += b.w;
    }
    *reinterpret_cast<float4*>(out + (size_t)t * H_DIM + h) =
        make_float4(s0.x + s1.x, s0.y + s1.y, s0.z + s1.z, s0.w + s1.w);
}

extern "C" void kernel_launch(void* const* d_in, const int* in_sizes, int n_in,
                              void* d_out, int out_size) {
    const float* x  = (const float*)d_in[0];
    const float* wg = (const float*)d_in[1];
    const float* w1 = (const float*)d_in[2];
    const float* w3 = (const float*)d_in[3];
    const float* w2 = (const float*)d_in[4];
    float* out = (float*)d_out;

    cudaFuncSetAttribute(gemm13_kernel, cudaFuncAttributeMaxDynamicSharedMemorySize, SMEM13);
    cudaFuncSetAttribute(gemm2_kernel, cudaFuncAttributeMaxDynamicSharedMemorySize, SMEM2);

    gate_kernel<<<T_TOK / 8, 256>>>(x, wg);
    route_scatter_kernel<<<1, 256>>>();
    gather_kernel<<<ROWS_CAP * 512 / 256, 256>>>(x);

    dim3 g1(F_DIM / 64, MTILES);
    gemm13_kernel<<<g1, 256, SMEM13>>>(w1, w3);

    dim3 g2(H_DIM / 128, MTILES, KSPLIT);
    gemm2_kernel<<<g2, 256, SMEM2>>>(w2);

    combine_kernel<<<(T_TOK * H_DIM / 4) / 256, 256>>>(out);
}